// round 4
// baseline (speedup 1.0000x reference)
#include <cuda_runtime.h>
#include <cstdint>
#include <cstddef>

// ---------------------------------------------------------------------------
// Problem constants (fixed by the reference)
// ---------------------------------------------------------------------------
namespace {
constexpr int kB    = 256;    // batch
constexpr int kTin  = 256;    // encoder steps
constexpr int kTout = 32;     // decoder steps
constexpr int kE    = 512;    // embedding dim
constexpr int kH    = 1024;   // hidden dim
constexpr int kY    = 1024;   // output feature dim
constexpr int kH3   = 3 * kH; // GRU gate width
}

// ---------------------------------------------------------------------------
// Scratch (device globals -- allocation-free rule)
// ---------------------------------------------------------------------------
__device__ float g_A0[(size_t)kTin * kB * kE];      // gathered embeddings  [T*B, E]
__device__ float g_gi[(size_t)kTin * kB * kH3];     // batched input gates  [T*B, 3H]
__device__ float g_seqA[(size_t)kTin * kB * kH];    // encoder layer0 outputs
__device__ float g_enc[(size_t)kTin * kB * kH];     // encoder layer1 outputs (enc_out)
__device__ float g_dgi[(size_t)kTout * kB * kH3];   // decoder L0 batched input gates
__device__ float g_ysin[(size_t)kTout * kB * kY];   // shifted teacher inputs
__device__ float g_h1[2][kB * kH];                  // ping-pong hidden (layer-A role)
__device__ float g_h2[2][kB * kH];                  // ping-pong hidden (layer-B role)
__device__ float g_cat[kB * 2 * kH];                // [attn | h2]
__device__ float g_logits[kB * kY];
__device__ float g_loss[kTout * kB];
__device__ float g_ypart[kTout * kB];
__device__ float g_ysum;

// ---------------------------------------------------------------------------
// Reduction helpers (blockDim.x == 256 assumed)
// ---------------------------------------------------------------------------
__device__ __forceinline__ float warp_sum(float v) {
#pragma unroll
    for (int o = 16; o; o >>= 1) v += __shfl_xor_sync(0xffffffffu, v, o);
    return v;
}
__device__ __forceinline__ float warp_max(float v) {
#pragma unroll
    for (int o = 16; o; o >>= 1) v = fmaxf(v, __shfl_xor_sync(0xffffffffu, v, o));
    return v;
}
// Deterministic block reductions: fixed shuffle tree + fixed scan order.
__device__ __forceinline__ float block_sum(float v, float* red) {
    int l = threadIdx.x & 31, w = threadIdx.x >> 5;
    v = warp_sum(v);
    if (l == 0) red[w] = v;
    __syncthreads();
    float s = 0.f;
#pragma unroll
    for (int i = 0; i < 8; i++) s += red[i];
    __syncthreads();
    return s;
}
__device__ __forceinline__ float block_max(float v, float* red) {
    int l = threadIdx.x & 31, w = threadIdx.x >> 5;
    v = warp_max(v);
    if (l == 0) red[w] = v;
    __syncthreads();
    float s = red[0];
#pragma unroll
    for (int i = 1; i < 8; i++) s = fmaxf(s, red[i]);
    __syncthreads();
    return s;
}
__device__ __forceinline__ float sigmoidf(float x) { return 1.0f / (1.0f + expf(-x)); }

// ---------------------------------------------------------------------------
// GEMM:  C[M,N] = A[M,K] * W[N,K]^T (+ bias[N])    both operands K-contiguous
// Tiles 64x64x16, 256 threads, 4x4 microtile, float4 smem/gmem paths.
// All M%64==0, N%64==0, K%16==0 by construction -> no bounds checks.
// Used only for the large time-batched GEMMs and the mapping GEMM.
// ---------------------------------------------------------------------------
__global__ void __launch_bounds__(256) gemm_nt(
    const float* __restrict__ A, const float* __restrict__ W,
    const float* __restrict__ bias, float* __restrict__ C,
    int M, int N, int K)
{
    constexpr int BM = 64, BN = 64, BK = 16;
    __shared__ float As[BK][BM + 4];
    __shared__ float Ws[BK][BN + 4];

    const int tid = threadIdx.x;
    const int tx = tid & 15, ty = tid >> 4;
    const int m0 = blockIdx.y * BM, n0 = blockIdx.x * BN;
    const int lrow = tid >> 2;          // 0..63
    const int lk   = (tid & 3) * 4;     // 0,4,8,12

    const float* Aptr = A + (size_t)(m0 + lrow) * K + lk;
    const float* Wptr = W + (size_t)(n0 + lrow) * K + lk;

    float acc[4][4] = {};
    for (int k0 = 0; k0 < K; k0 += BK) {
        float4 av = *(const float4*)(Aptr + k0);
        float4 wv = *(const float4*)(Wptr + k0);
        As[lk + 0][lrow] = av.x; As[lk + 1][lrow] = av.y;
        As[lk + 2][lrow] = av.z; As[lk + 3][lrow] = av.w;
        Ws[lk + 0][lrow] = wv.x; Ws[lk + 1][lrow] = wv.y;
        Ws[lk + 2][lrow] = wv.z; Ws[lk + 3][lrow] = wv.w;
        __syncthreads();
#pragma unroll
        for (int k = 0; k < BK; k++) {
            float4 a = *(const float4*)&As[k][ty * 4];
            float4 b = *(const float4*)&Ws[k][tx * 4];
            const float* af = (const float*)&a;
            const float* bf = (const float*)&b;
#pragma unroll
            for (int i = 0; i < 4; i++)
#pragma unroll
                for (int j = 0; j < 4; j++)
                    acc[i][j] += af[i] * bf[j];
        }
        __syncthreads();
    }

    float4 bv = make_float4(0.f, 0.f, 0.f, 0.f);
    if (bias) bv = *(const float4*)(bias + n0 + tx * 4);
#pragma unroll
    for (int i = 0; i < 4; i++) {
        float4 o;
        o.x = acc[i][0] + bv.x; o.y = acc[i][1] + bv.y;
        o.z = acc[i][2] + bv.z; o.w = acc[i][3] + bv.w;
        *(float4*)(C + (size_t)(m0 + ty * 4 + i) * N + n0 + tx * 4) = o;
    }
}

// ---------------------------------------------------------------------------
// FUSED GRU STEP (precomputed input gates):
//   gh = h_old @ Whh^T + bhh   (3 gate slabs computed in-register)
//   r,z,n gates with precomputed gi (bih already folded in)
//   h_new = (1-z)*n + z*h_old
// Tiles: BM=64 batch rows x BN=32 hidden cols x 3 gate slabs, BK=16.
// Grid (kH/32, kB/64) = (32,4) = 128 blocks -> one full wave.
// Reads h_old, writes h_new (ping-pong -> no cross-block hazard).
// ---------------------------------------------------------------------------
__global__ void __launch_bounds__(256) gru_step_fused(
    const float* __restrict__ gi, const float* __restrict__ Whh,
    const float* __restrict__ bhh, const float* __restrict__ h_old,
    float* __restrict__ h_new, float* __restrict__ seq_out)
{
    constexpr int BM = 64, BN = 32, BK = 16;
    __shared__ float As[BK][BM + 4];
    __shared__ float Ws[3][BK][BN + 4];

    const int tid = threadIdx.x;
    const int m0 = blockIdx.y * BM, n0 = blockIdx.x * BN;
    const int lrow = tid >> 2;          // 0..63
    const int lk   = (tid & 3) * 4;     // 0,4,8,12
    const int tx = tid & 7;             // col group (4 cols)
    const int ty = tid >> 3;            // row pair (2 rows)

    const float* hA = h_old + (size_t)(m0 + lrow) * kH + lk;

    float acc[3][2][4] = {};
    for (int k0 = 0; k0 < kH; k0 += BK) {
        float4 av = *(const float4*)(hA + k0);
        As[lk + 0][lrow] = av.x; As[lk + 1][lrow] = av.y;
        As[lk + 2][lrow] = av.z; As[lk + 3][lrow] = av.w;
        for (int i = tid; i < 384; i += 256) {       // 3 gates * 32 rows * 4 f4
            int g  = i >> 7;
            int rr = (i >> 2) & 31;
            int kk = (i & 3) * 4;
            float4 wv = *(const float4*)(Whh + (size_t)(g * kH + n0 + rr) * kH + k0 + kk);
            Ws[g][kk + 0][rr] = wv.x; Ws[g][kk + 1][rr] = wv.y;
            Ws[g][kk + 2][rr] = wv.z; Ws[g][kk + 3][rr] = wv.w;
        }
        __syncthreads();
#pragma unroll
        for (int k = 0; k < BK; k++) {
            float a0 = As[k][ty * 2 + 0];
            float a1 = As[k][ty * 2 + 1];
#pragma unroll
            for (int g = 0; g < 3; g++) {
                float4 w = *(const float4*)&Ws[g][k][tx * 4];
                acc[g][0][0] += a0 * w.x; acc[g][0][1] += a0 * w.y;
                acc[g][0][2] += a0 * w.z; acc[g][0][3] += a0 * w.w;
                acc[g][1][0] += a1 * w.x; acc[g][1][1] += a1 * w.y;
                acc[g][1][2] += a1 * w.z; acc[g][1][3] += a1 * w.w;
            }
        }
        __syncthreads();
    }

    const int j = n0 + tx * 4;
    const float4 br = *(const float4*)(bhh + j);
    const float4 bz = *(const float4*)(bhh + kH + j);
    const float4 bn = *(const float4*)(bhh + 2 * kH + j);
#pragma unroll
    for (int mi = 0; mi < 2; mi++) {
        const int b = m0 + ty * 2 + mi;
        const float* gib = gi + (size_t)b * kH3;
        float4 gr = *(const float4*)(gib + j);
        float4 gz = *(const float4*)(gib + kH + j);
        float4 gn = *(const float4*)(gib + 2 * kH + j);
        float4 hv = *(const float4*)(h_old + (size_t)b * kH + j);
        float4 o;
        float* op = (float*)&o;
        const float* grp = (const float*)&gr; const float* gzp = (const float*)&gz;
        const float* gnp = (const float*)&gn; const float* hvp = (const float*)&hv;
        const float* brp = (const float*)&br; const float* bzp = (const float*)&bz;
        const float* bnp = (const float*)&bn;
#pragma unroll
        for (int c = 0; c < 4; c++) {
            float r = sigmoidf(grp[c] + acc[0][mi][c] + brp[c]);
            float z = sigmoidf(gzp[c] + acc[1][mi][c] + bzp[c]);
            float n = tanhf(gnp[c] + r * (acc[2][mi][c] + bnp[c]));
            op[c] = (1.0f - z) * n + z * hvp[c];
        }
        *(float4*)(h_new + (size_t)b * kH + j) = o;
        if (seq_out) *(float4*)(seq_out + (size_t)b * kH + j) = o;
    }
}

// ---------------------------------------------------------------------------
// FUSED DUAL-GEMM GRU STEP (decoder layer 1):
//   gi = x @ Wih^T + bih,  gh = h_old @ Whh^T + bhh  (6 slabs in-register)
//   h_new = (1-z)*n + z*h_old ; also writes cat_out[b*2H + j] = h_new
// ---------------------------------------------------------------------------
__global__ void __launch_bounds__(256) gru_step_dual(
    const float* __restrict__ x,   const float* __restrict__ Wih,
    const float* __restrict__ bih, const float* __restrict__ h_old,
    const float* __restrict__ Whh, const float* __restrict__ bhh,
    float* __restrict__ h_new,     float* __restrict__ cat_out)
{
    constexpr int BM = 64, BN = 32, BK = 16;
    __shared__ float As[2][BK][BM + 4];          // [0]=x, [1]=h
    __shared__ float Ws[6][BK][BN + 4];          // [0..2]=Wih, [3..5]=Whh

    const int tid = threadIdx.x;
    const int m0 = blockIdx.y * BM, n0 = blockIdx.x * BN;
    const int lrow = tid >> 2;
    const int lk   = (tid & 3) * 4;
    const int tx = tid & 7;
    const int ty = tid >> 3;

    const float* xA = x     + (size_t)(m0 + lrow) * kH + lk;
    const float* hA = h_old + (size_t)(m0 + lrow) * kH + lk;

    float acc[6][2][4] = {};
    for (int k0 = 0; k0 < kH; k0 += BK) {
        float4 av = *(const float4*)(xA + k0);
        As[0][lk + 0][lrow] = av.x; As[0][lk + 1][lrow] = av.y;
        As[0][lk + 2][lrow] = av.z; As[0][lk + 3][lrow] = av.w;
        float4 hv = *(const float4*)(hA + k0);
        As[1][lk + 0][lrow] = hv.x; As[1][lk + 1][lrow] = hv.y;
        As[1][lk + 2][lrow] = hv.z; As[1][lk + 3][lrow] = hv.w;
        for (int i = tid; i < 768; i += 256) {   // 6 slabs * 32 rows * 4 f4
            int s  = i >> 7;                      // 0..5
            int rr = (i >> 2) & 31;
            int kk = (i & 3) * 4;
            const float* Wsrc = (s < 3) ? Wih : Whh;
            int g = (s < 3) ? s : s - 3;
            float4 wv = *(const float4*)(Wsrc + (size_t)(g * kH + n0 + rr) * kH + k0 + kk);
            Ws[s][kk + 0][rr] = wv.x; Ws[s][kk + 1][rr] = wv.y;
            Ws[s][kk + 2][rr] = wv.z; Ws[s][kk + 3][rr] = wv.w;
        }
        __syncthreads();
#pragma unroll
        for (int k = 0; k < BK; k++) {
            float a0x = As[0][k][ty * 2 + 0];
            float a1x = As[0][k][ty * 2 + 1];
            float a0h = As[1][k][ty * 2 + 0];
            float a1h = As[1][k][ty * 2 + 1];
#pragma unroll
            for (int s = 0; s < 6; s++) {
                float4 w = *(const float4*)&Ws[s][k][tx * 4];
                float a0 = (s < 3) ? a0x : a0h;
                float a1 = (s < 3) ? a1x : a1h;
                acc[s][0][0] += a0 * w.x; acc[s][0][1] += a0 * w.y;
                acc[s][0][2] += a0 * w.z; acc[s][0][3] += a0 * w.w;
                acc[s][1][0] += a1 * w.x; acc[s][1][1] += a1 * w.y;
                acc[s][1][2] += a1 * w.z; acc[s][1][3] += a1 * w.w;
            }
        }
        __syncthreads();
    }

    const int j = n0 + tx * 4;
    const float4 bir = *(const float4*)(bih + j);
    const float4 biz = *(const float4*)(bih + kH + j);
    const float4 bin = *(const float4*)(bih + 2 * kH + j);
    const float4 bhr = *(const float4*)(bhh + j);
    const float4 bhz = *(const float4*)(bhh + kH + j);
    const float4 bhn = *(const float4*)(bhh + 2 * kH + j);
#pragma unroll
    for (int mi = 0; mi < 2; mi++) {
        const int b = m0 + ty * 2 + mi;
        float4 hv = *(const float4*)(h_old + (size_t)b * kH + j);
        float4 o;
        float* op = (float*)&o;
        const float* hvp = (const float*)&hv;
        const float* birp = (const float*)&bir; const float* bizp = (const float*)&biz;
        const float* binp = (const float*)&bin; const float* bhrp = (const float*)&bhr;
        const float* bhzp = (const float*)&bhz; const float* bhnp = (const float*)&bhn;
#pragma unroll
        for (int c = 0; c < 4; c++) {
            float r = sigmoidf(acc[0][mi][c] + birp[c] + acc[3][mi][c] + bhrp[c]);
            float z = sigmoidf(acc[1][mi][c] + bizp[c] + acc[4][mi][c] + bhzp[c]);
            float n = tanhf(acc[2][mi][c] + binp[c] + r * (acc[5][mi][c] + bhnp[c]));
            op[c] = (1.0f - z) * n + z * hvp[c];
        }
        *(float4*)(h_new + (size_t)b * kH + j) = o;
        *(float4*)(cat_out + (size_t)b * 2 * kH + j) = o;
    }
}

// ---------------------------------------------------------------------------
// Embedding gather: g_A0[(t*B+b)*E + e] = emb[x[b,t]][e]
// ---------------------------------------------------------------------------
__global__ void gather_emb(const float* __restrict__ emb, const int* __restrict__ x)
{
    int idx = blockIdx.x * blockDim.x + threadIdx.x;  // over T*B*E/4
    int col = idx & (kE / 4 - 1);
    int row = idx >> 7;            // E/4 = 128
    int t = row >> 8;              // /kB
    int b = row & (kB - 1);
    int tok = x[b * kTin + t];
    ((float4*)g_A0)[idx] = ((const float4*)emb)[(size_t)tok * (kE / 4) + col];
}

// ---------------------------------------------------------------------------
// Teacher-forcing shift: ys_in[t,b,:] = (t==0) ? 0 : y[b,t-1,:]
// ---------------------------------------------------------------------------
__global__ void build_ysin(const float* __restrict__ y)
{
    int idx = blockIdx.x * blockDim.x + threadIdx.x;  // over Tout*B*Y/4
    int col = idx & (kY / 4 - 1);
    int row = idx >> 8;            // Y/4 = 256
    int t = row >> 8;              // /kB
    int b = row & (kB - 1);
    float4 v = make_float4(0.f, 0.f, 0.f, 0.f);
    if (t > 0) v = ((const float4*)y)[((size_t)b * kTout + (t - 1)) * (kY / 4) + col];
    ((float4*)g_ysin)[idx] = v;
}

__global__ void zero_state()
{
    int i = blockIdx.x * blockDim.x + threadIdx.x;
    g_h1[0][i] = 0.f; g_h2[0][i] = 0.f;
}

// ---------------------------------------------------------------------------
// y.sum() : deterministic two-stage reduction
// ---------------------------------------------------------------------------
__global__ void ysum_part(const float* __restrict__ y)
{
    __shared__ float red[8];
    int blk = blockIdx.x, tid = threadIdx.x;
    const float* p = y + (size_t)blk * 1024;
    float s = p[tid] + p[tid + 256] + p[tid + 512] + p[tid + 768];
    s = block_sum(s, red);
    if (tid == 0) g_ypart[blk] = s;
}
__global__ void ysum_final()
{
    __shared__ float red[8];
    int tid = threadIdx.x;
    float s = 0.f;
    for (int i = tid; i < kTout * kB; i += 256) s += g_ypart[i];
    s = block_sum(s, red);
    if (tid == 0) g_ysum = s;
}

// ---------------------------------------------------------------------------
// Attention (per decoder step): one block per batch row.
//  pass1: scores[s] = <enc_out[s,b,:], h2[b,:]>  (warp-per-32-scores)
//  softmax in smem, pass2: attn[h] = sum_s p_s enc_out[s,b,h]  (coalesced)
// Writes cat[b, 0:H] = attn.   (cat[b, H:2H] = h2 written by gru_step_dual.)
// ---------------------------------------------------------------------------
__global__ void attn_kernel(const float* __restrict__ h2)
{
    __shared__ float sh[kH];
    __shared__ float sc[kTin];
    __shared__ float red[16];
    int b = blockIdx.x, tid = threadIdx.x;
    int w = tid >> 5, l = tid & 31;

#pragma unroll
    for (int q = 0; q < 4; q++) sh[tid + 256 * q] = h2[b * kH + tid + 256 * q];
    __syncthreads();

    for (int si = 0; si < 32; si++) {
        int s = w * 32 + si;
        const float* row = g_enc + ((size_t)s * kB + b) * kH;
        float acc = 0.f;
#pragma unroll 8
        for (int k = 0; k < 32; k++) acc += row[l + 32 * k] * sh[l + 32 * k];
        acc = warp_sum(acc);
        if (l == 0) sc[s] = acc;
    }
    __syncthreads();

    float v = sc[tid];
    float m = warp_max(v);
    if (l == 0) red[w] = m;
    __syncthreads();
    float bm = red[0];
#pragma unroll
    for (int i = 1; i < 8; i++) bm = fmaxf(bm, red[i]);
    float p = expf(v - bm);
    sc[tid] = p;
    float ps = warp_sum(p);
    if (l == 0) red[8 + w] = ps;
    __syncthreads();
    float tot = 0.f;
#pragma unroll
    for (int i = 0; i < 8; i++) tot += red[8 + i];

    float a0 = 0.f, a1 = 0.f, a2 = 0.f, a3 = 0.f;
#pragma unroll 4
    for (int s = 0; s < kTin; s++) {
        float pr = sc[s];
        const float* row = g_enc + ((size_t)s * kB + b) * kH;
        a0 += pr * row[tid];       a1 += pr * row[tid + 256];
        a2 += pr * row[tid + 512]; a3 += pr * row[tid + 768];
    }
    float inv = 1.0f / tot;
    float* cb = g_cat + b * 2 * kH;
    cb[tid] = a0 * inv; cb[tid + 256] = a1 * inv;
    cb[tid + 512] = a2 * inv; cb[tid + 768] = a3 * inv;
}

// ---------------------------------------------------------------------------
// Per-step NLL: loss[t,b] = sum_v y[b,t,v] * (logsumexp(logits[b,:]) - logits[b,v])
// ---------------------------------------------------------------------------
__global__ void loss_kernel(const float* __restrict__ y, int t)
{
    __shared__ float red[8];
    int b = blockIdx.x, tid = threadIdx.x;
    const float* lr = g_logits + b * kY;
    float l0 = lr[tid], l1 = lr[tid + 256], l2 = lr[tid + 512], l3 = lr[tid + 768];
    float m = block_max(fmaxf(fmaxf(l0, l1), fmaxf(l2, l3)), red);
    float se = block_sum(expf(l0 - m) + expf(l1 - m) + expf(l2 - m) + expf(l3 - m), red);
    float lse = m + logf(se);
    const float* yr = y + ((size_t)b * kTout + t) * kY;
    float a = yr[tid] * (lse - l0) + yr[tid + 256] * (lse - l1)
            + yr[tid + 512] * (lse - l2) + yr[tid + 768] * (lse - l3);
    a = block_sum(a, red);
    if (tid == 0) g_loss[t * kB + b] = a;
}

__global__ void final_kernel(float* __restrict__ out)
{
    __shared__ float red[8];
    int tid = threadIdx.x;
    float s = 0.f;
    for (int i = tid; i < kTout * kB; i += 256) s += g_loss[i];
    s = block_sum(s, red);
    if (tid == 0) out[0] = s / g_ysum;
}

// ---------------------------------------------------------------------------
// Orchestration
// ---------------------------------------------------------------------------
extern "C" void kernel_launch(void* const* d_in, const int* in_sizes, int n_in,
                              void* d_out, int out_size)
{
    const int*   x    = (const int*)d_in[0];
    const float* y    = (const float*)d_in[1];
    const float* emb  = (const float*)d_in[2];
    const float* eWih0 = (const float*)d_in[3],  *eWhh0 = (const float*)d_in[4];
    const float* ebih0 = (const float*)d_in[5],  *ebhh0 = (const float*)d_in[6];
    const float* eWih1 = (const float*)d_in[7],  *eWhh1 = (const float*)d_in[8];
    const float* ebih1 = (const float*)d_in[9],  *ebhh1 = (const float*)d_in[10];
    const float* dWih0 = (const float*)d_in[11], *dWhh0 = (const float*)d_in[12];
    const float* dbih0 = (const float*)d_in[13], *dbhh0 = (const float*)d_in[14];
    const float* dWih1 = (const float*)d_in[15], *dWhh1 = (const float*)d_in[16];
    const float* dbih1 = (const float*)d_in[17], *dbhh1 = (const float*)d_in[18];
    const float* mapW  = (const float*)d_in[19], *mapb  = (const float*)d_in[20];
    float* out = (float*)d_out;

    // cudaGetSymbolAddress performs no stream work -> capture-legal.
    float *pA0, *pgi, *pseqA, *penc, *pdgi, *pysin, *ph1, *ph2, *pcat, *plogits;
    cudaGetSymbolAddress((void**)&pA0, g_A0);
    cudaGetSymbolAddress((void**)&pgi, g_gi);
    cudaGetSymbolAddress((void**)&pseqA, g_seqA);
    cudaGetSymbolAddress((void**)&penc, g_enc);
    cudaGetSymbolAddress((void**)&pdgi, g_dgi);
    cudaGetSymbolAddress((void**)&pysin, g_ysin);
    cudaGetSymbolAddress((void**)&ph1, g_h1);
    cudaGetSymbolAddress((void**)&ph2, g_h2);
    cudaGetSymbolAddress((void**)&pcat, g_cat);
    cudaGetSymbolAddress((void**)&plogits, g_logits);

    float* h1buf[2] = { ph1, ph1 + (size_t)kB * kH };
    float* h2buf[2] = { ph2, ph2 + (size_t)kB * kH };

    // ---- phase 0: init + batchable precomputation ----
    zero_state<<<kB * kH / 256, 256>>>();
    gather_emb<<<(kTin * kB * kE / 4) / 256, 256>>>(emb, x);
    ysum_part<<<kTout * kB, 256>>>(y);
    ysum_final<<<1, 256>>>();
    build_ysin<<<(kTout * kB * kY / 4) / 256, 256>>>(y);

    const dim3 gBig(kH3 / 64, kTin * kB / 64);   // 48 x 1024
    const dim3 gDec(kH3 / 64, kTout * kB / 64);  // 48 x 128
    const dim3 gMap(kY / 64, kB / 64);           // 16 x 4
    const dim3 gFus(kH / 32, kB / 64);           // 32 x 4 = 128 blocks

    // ---- encoder layer 0 ----  (h role: g_h1 ping-pong, parity p1)
    int p1 = 0, p2 = 0;
    gemm_nt<<<gBig, 256>>>(pA0, eWih0, ebih0, pgi, kTin * kB, kH3, kE);
    for (int t = 0; t < kTin; t++) {
        gru_step_fused<<<gFus, 256>>>(pgi + (size_t)t * kB * kH3, eWhh0, ebhh0,
                                      h1buf[p1], h1buf[p1 ^ 1],
                                      pseqA + (size_t)t * kB * kH);
        p1 ^= 1;
    }
    // ---- encoder layer 1 ----  (h role: g_h2 ping-pong; initial h = 0)
    gemm_nt<<<gBig, 256>>>(pseqA, eWih1, ebih1, pgi, kTin * kB, kH3, kH);
    for (int t = 0; t < kTin; t++) {
        gru_step_fused<<<gFus, 256>>>(pgi + (size_t)t * kB * kH3, eWhh1, ebhh1,
                                      h2buf[p2], h2buf[p2 ^ 1],
                                      penc + (size_t)t * kB * kH);
        p2 ^= 1;
    }
    // h1buf[p1] = encoder L0 final hidden, h2buf[p2] = encoder L1 final hidden.

    // ---- decoder (teacher-forced input gates precomputed) ----
    gemm_nt<<<gDec, 256>>>(pysin, dWih0, dbih0, pdgi, kTout * kB, kH3, kY);
    for (int t = 0; t < kTout; t++) {
        gru_step_fused<<<gFus, 256>>>(pdgi + (size_t)t * kB * kH3, dWhh0, dbhh0,
                                      h1buf[p1], h1buf[p1 ^ 1], nullptr);
        p1 ^= 1;
        gru_step_dual<<<gFus, 256>>>(h1buf[p1], dWih1, dbih1,
                                     h2buf[p2], dWhh1, dbhh1,
                                     h2buf[p2 ^ 1], pcat + kH);
        p2 ^= 1;
        attn_kernel<<<kB, 256>>>(h2buf[p2]);              // fills cat[:,0:H]
        gemm_nt<<<gMap, 256>>>(pcat, mapW, mapb, plogits, kB, kY, 2 * kH);
        loss_kernel<<<kB, 256>>>(y, t);
    }
    final_kernel<<<1, 256>>>(out);
}

// round 6
// speedup vs baseline: 1.0318x; 1.0318x over previous
#include <cuda_runtime.h>
#include <cstdint>
#include <cstddef>

// ---------------------------------------------------------------------------
// Problem constants (fixed by the reference)
// ---------------------------------------------------------------------------
namespace {
constexpr int kB    = 256;    // batch
constexpr int kTin  = 256;    // encoder steps
constexpr int kTout = 32;     // decoder steps
constexpr int kE    = 512;    // embedding dim
constexpr int kH    = 1024;   // hidden dim
constexpr int kY    = 1024;   // output feature dim
constexpr int kH3   = 3 * kH; // GRU gate width
}

// ---------------------------------------------------------------------------
// Scratch (device globals -- allocation-free rule)
// ---------------------------------------------------------------------------
__device__ float g_A0[(size_t)kTin * kB * kE];      // gathered embeddings  [T*B, E]
__device__ float g_gi[(size_t)kTin * kB * kH3];     // enc L0 batched input gates
__device__ float g_seqA[(size_t)kTin * kB * kH];    // encoder layer0 outputs
__device__ float g_enc[(size_t)kTin * kB * kH];     // encoder layer1 outputs (enc_out)
__device__ float g_dgi[(size_t)kTout * kB * kH3];   // decoder L0 batched input gates
__device__ float g_ysin[(size_t)kTout * kB * kY];   // shifted teacher inputs
__device__ float g_h1[2][kB * kH];                  // ping-pong hidden (layer-A role)
__device__ float g_h2[2][kB * kH];                  // ping-pong hidden (layer-B role)
__device__ float g_cat[kB * 2 * kH];                // [attn | h2]
__device__ float g_logits[kB * kY];
__device__ float g_loss[kTout * kB];
__device__ float g_ypart[kTout * kB];
__device__ float g_ysum;

// ---------------------------------------------------------------------------
// Reduction helpers (blockDim.x == 256 assumed)
// ---------------------------------------------------------------------------
__device__ __forceinline__ float warp_sum(float v) {
#pragma unroll
    for (int o = 16; o; o >>= 1) v += __shfl_xor_sync(0xffffffffu, v, o);
    return v;
}
__device__ __forceinline__ float warp_max(float v) {
#pragma unroll
    for (int o = 16; o; o >>= 1) v = fmaxf(v, __shfl_xor_sync(0xffffffffu, v, o));
    return v;
}
__device__ __forceinline__ float block_sum(float v, float* red) {
    int l = threadIdx.x & 31, w = threadIdx.x >> 5;
    v = warp_sum(v);
    if (l == 0) red[w] = v;
    __syncthreads();
    float s = 0.f;
#pragma unroll
    for (int i = 0; i < 8; i++) s += red[i];
    __syncthreads();
    return s;
}
__device__ __forceinline__ float block_max(float v, float* red) {
    int l = threadIdx.x & 31, w = threadIdx.x >> 5;
    v = warp_max(v);
    if (l == 0) red[w] = v;
    __syncthreads();
    float s = red[0];
#pragma unroll
    for (int i = 1; i < 8; i++) s = fmaxf(s, red[i]);
    __syncthreads();
    return s;
}
__device__ __forceinline__ float sigmoidf(float x) { return 1.0f / (1.0f + expf(-x)); }

// ---------------------------------------------------------------------------
// GEMM:  C[M,N] = A[M,K] * W[N,K]^T (+ bias[N])    both operands K-contiguous
// 64x64x16 tiles, 256 threads, 4x4 microtile. (time-batched + mapping GEMMs)
// ---------------------------------------------------------------------------
__global__ void __launch_bounds__(256) gemm_nt(
    const float* __restrict__ A, const float* __restrict__ W,
    const float* __restrict__ bias, float* __restrict__ C,
    int M, int N, int K)
{
    constexpr int BM = 64, BN = 64, BK = 16;
    __shared__ float As[BK][BM + 4];
    __shared__ float Ws[BK][BN + 4];

    const int tid = threadIdx.x;
    const int tx = tid & 15, ty = tid >> 4;
    const int m0 = blockIdx.y * BM, n0 = blockIdx.x * BN;
    const int lrow = tid >> 2;          // 0..63
    const int lk   = (tid & 3) * 4;     // 0,4,8,12

    const float* Aptr = A + (size_t)(m0 + lrow) * K + lk;
    const float* Wptr = W + (size_t)(n0 + lrow) * K + lk;

    float acc[4][4] = {};
    for (int k0 = 0; k0 < K; k0 += BK) {
        float4 av = *(const float4*)(Aptr + k0);
        float4 wv = *(const float4*)(Wptr + k0);
        As[lk + 0][lrow] = av.x; As[lk + 1][lrow] = av.y;
        As[lk + 2][lrow] = av.z; As[lk + 3][lrow] = av.w;
        Ws[lk + 0][lrow] = wv.x; Ws[lk + 1][lrow] = wv.y;
        Ws[lk + 2][lrow] = wv.z; Ws[lk + 3][lrow] = wv.w;
        __syncthreads();
#pragma unroll
        for (int k = 0; k < BK; k++) {
            float4 a = *(const float4*)&As[k][ty * 4];
            float4 b = *(const float4*)&Ws[k][tx * 4];
            const float* af = (const float*)&a;
            const float* bf = (const float*)&b;
#pragma unroll
            for (int i = 0; i < 4; i++)
#pragma unroll
                for (int j = 0; j < 4; j++)
                    acc[i][j] += af[i] * bf[j];
        }
        __syncthreads();
    }

    float4 bv = make_float4(0.f, 0.f, 0.f, 0.f);
    if (bias) bv = *(const float4*)(bias + n0 + tx * 4);
#pragma unroll
    for (int i = 0; i < 4; i++) {
        float4 o;
        o.x = acc[i][0] + bv.x; o.y = acc[i][1] + bv.y;
        o.z = acc[i][2] + bv.z; o.w = acc[i][3] + bv.w;
        *(float4*)(C + (size_t)(m0 + ty * 4 + i) * N + n0 + tx * 4) = o;
    }
}

// ---------------------------------------------------------------------------
// 512-thread fused GRU step tile (BM=64 batch x BN=32 hidden x 3 gate slabs):
//   gh = h_old @ Whh^T (+bhh in epilogue); gi precomputed (bih folded in).
//   h_new = (1-z)*n + z*h_old.  One output row x 4 cols per thread.
// Shared layout (floats): As[16][68] at sA;  Ws[3][16][36] at sW.
// ---------------------------------------------------------------------------
__device__ __forceinline__ void gru_fused_tile(
    float* sA, float* sW,
    const float* __restrict__ gi, const float* __restrict__ Whh,
    const float* __restrict__ bhh, const float* __restrict__ h_old,
    float* __restrict__ h_new, float* __restrict__ seq_out,
    int bx, int by)
{
    const int tid = threadIdx.x;
    const int m0 = by * 64, n0 = bx * 32;
    const int tx = tid & 7, ty = tid >> 3;       // 8 col-groups x 64 rows

    float acc[3][4] = {};
    for (int k0 = 0; k0 < kH; k0 += 16) {
        if (tid < 256) {
            int lrow = tid >> 2, lk = (tid & 3) * 4;
            float4 av = *(const float4*)(h_old + (size_t)(m0 + lrow) * kH + k0 + lk);
            sA[(lk + 0) * 68 + lrow] = av.x; sA[(lk + 1) * 68 + lrow] = av.y;
            sA[(lk + 2) * 68 + lrow] = av.z; sA[(lk + 3) * 68 + lrow] = av.w;
        }
        if (tid < 384) {
            int g = tid >> 7, rr = (tid >> 2) & 31, kk = (tid & 3) * 4;
            float4 wv = *(const float4*)(Whh + (size_t)(g * kH + n0 + rr) * kH + k0 + kk);
            sW[(g * 16 + kk + 0) * 36 + rr] = wv.x; sW[(g * 16 + kk + 1) * 36 + rr] = wv.y;
            sW[(g * 16 + kk + 2) * 36 + rr] = wv.z; sW[(g * 16 + kk + 3) * 36 + rr] = wv.w;
        }
        __syncthreads();
#pragma unroll
        for (int k = 0; k < 16; k++) {
            float a = sA[k * 68 + ty];
#pragma unroll
            for (int g = 0; g < 3; g++) {
                float4 w = *(const float4*)&sW[(g * 16 + k) * 36 + tx * 4];
                acc[g][0] += a * w.x; acc[g][1] += a * w.y;
                acc[g][2] += a * w.z; acc[g][3] += a * w.w;
            }
        }
        __syncthreads();
    }

    const int b = m0 + ty, j = n0 + tx * 4;
    const float4 br = *(const float4*)(bhh + j);
    const float4 bz = *(const float4*)(bhh + kH + j);
    const float4 bn = *(const float4*)(bhh + 2 * kH + j);
    const float* gib = gi + (size_t)b * kH3;
    float4 gr = *(const float4*)(gib + j);
    float4 gz = *(const float4*)(gib + kH + j);
    float4 gn = *(const float4*)(gib + 2 * kH + j);
    float4 hv = *(const float4*)(h_old + (size_t)b * kH + j);
    float4 o;
    float* op = (float*)&o;
    const float* grp = (const float*)&gr; const float* gzp = (const float*)&gz;
    const float* gnp = (const float*)&gn; const float* hvp = (const float*)&hv;
    const float* brp = (const float*)&br; const float* bzp = (const float*)&bz;
    const float* bnp = (const float*)&bn;
#pragma unroll
    for (int c = 0; c < 4; c++) {
        float r = sigmoidf(grp[c] + acc[0][c] + brp[c]);
        float z = sigmoidf(gzp[c] + acc[1][c] + bzp[c]);
        float n = tanhf(gnp[c] + r * (acc[2][c] + bnp[c]));
        op[c] = (1.0f - z) * n + z * hvp[c];
    }
    *(float4*)(h_new + (size_t)b * kH + j) = o;
    if (seq_out) *(float4*)(seq_out + (size_t)b * kH + j) = o;
}

// ---------------------------------------------------------------------------
// 512-thread dual-GEMM GRU step tile (x @ Wih^T and h @ Whh^T, 6 slabs):
// Shared: As2[2][16][68] at sA (second buffer at +1088); Ws[6][16][36] at sW.
// ---------------------------------------------------------------------------
__device__ __forceinline__ void gru_dual_tile(
    float* sA, float* sW,
    const float* __restrict__ x,   const float* __restrict__ Wih,
    const float* __restrict__ bih, const float* __restrict__ h_old,
    const float* __restrict__ Whh, const float* __restrict__ bhh,
    float* __restrict__ h_new, float* __restrict__ seq_out,
    float* __restrict__ cat_out, int bx, int by)
{
    const int tid = threadIdx.x;
    const int m0 = by * 64, n0 = bx * 32;
    const int tx = tid & 7, ty = tid >> 3;

    float acc[6][4] = {};
    for (int k0 = 0; k0 < kH; k0 += 16) {
        {   // stage both A tiles: 512 threads cover 2 bufs x 64 rows x 4 f4
            int buf = tid >> 8, rr = (tid >> 2) & 63, kk = (tid & 3) * 4;
            const float* src = buf ? h_old : x;
            float4 av = *(const float4*)(src + (size_t)(m0 + rr) * kH + k0 + kk);
            float* dst = sA + buf * 1088;
            dst[(kk + 0) * 68 + rr] = av.x; dst[(kk + 1) * 68 + rr] = av.y;
            dst[(kk + 2) * 68 + rr] = av.z; dst[(kk + 3) * 68 + rr] = av.w;
        }
        for (int i = tid; i < 768; i += 512) {   // 6 slabs x 32 rows x 4 f4
            int s = i >> 7, rr = (i >> 2) & 31, kk = (i & 3) * 4;
            const float* Wsrc = (s < 3) ? Wih : Whh;
            int g = (s < 3) ? s : s - 3;
            float4 wv = *(const float4*)(Wsrc + (size_t)(g * kH + n0 + rr) * kH + k0 + kk);
            sW[(s * 16 + kk + 0) * 36 + rr] = wv.x; sW[(s * 16 + kk + 1) * 36 + rr] = wv.y;
            sW[(s * 16 + kk + 2) * 36 + rr] = wv.z; sW[(s * 16 + kk + 3) * 36 + rr] = wv.w;
        }
        __syncthreads();
#pragma unroll
        for (int k = 0; k < 16; k++) {
            float ax = sA[k * 68 + ty];
            float ah = sA[1088 + k * 68 + ty];
#pragma unroll
            for (int s = 0; s < 6; s++) {
                float4 w = *(const float4*)&sW[(s * 16 + k) * 36 + tx * 4];
                float a = (s < 3) ? ax : ah;
                acc[s][0] += a * w.x; acc[s][1] += a * w.y;
                acc[s][2] += a * w.z; acc[s][3] += a * w.w;
            }
        }
        __syncthreads();
    }

    const int b = m0 + ty, j = n0 + tx * 4;
    const float4 bir = *(const float4*)(bih + j);
    const float4 biz = *(const float4*)(bih + kH + j);
    const float4 bin = *(const float4*)(bih + 2 * kH + j);
    const float4 bhr = *(const float4*)(bhh + j);
    const float4 bhz = *(const float4*)(bhh + kH + j);
    const float4 bhn = *(const float4*)(bhh + 2 * kH + j);
    float4 hv = *(const float4*)(h_old + (size_t)b * kH + j);
    float4 o;
    float* op = (float*)&o;
    const float* hvp = (const float*)&hv;
    const float* birp = (const float*)&bir; const float* bizp = (const float*)&biz;
    const float* binp = (const float*)&bin; const float* bhrp = (const float*)&bhr;
    const float* bhzp = (const float*)&bhz; const float* bhnp = (const float*)&bhn;
#pragma unroll
    for (int c = 0; c < 4; c++) {
        float r = sigmoidf(acc[0][c] + birp[c] + acc[3][c] + bhrp[c]);
        float z = sigmoidf(acc[1][c] + bizp[c] + acc[4][c] + bhzp[c]);
        float n = tanhf(acc[2][c] + binp[c] + r * (acc[5][c] + bhnp[c]));
        op[c] = (1.0f - z) * n + z * hvp[c];
    }
    *(float4*)(h_new + (size_t)b * kH + j) = o;
    if (seq_out) *(float4*)(seq_out + (size_t)b * kH + j) = o;
    if (cat_out) *(float4*)(cat_out + (size_t)b * 2 * kH + j) = o;
}

// ---------------------------------------------------------------------------
// Encoder pipelined pair: z=0 -> L0 step t (fused), z=1 -> L1 step t-1 (dual).
// Grid (32, 4, 2) x 512 threads = 256 blocks.
// ---------------------------------------------------------------------------
__global__ void __launch_bounds__(512) enc_pair(
    const float* __restrict__ gi0, const float* __restrict__ Whh0,
    const float* __restrict__ bhh0, const float* __restrict__ h1_old,
    float* __restrict__ h1_new, float* __restrict__ seqA_t,
    const float* __restrict__ x1, const float* __restrict__ Wih1,
    const float* __restrict__ bih1, const float* __restrict__ h2_old,
    const float* __restrict__ Whh1, const float* __restrict__ bhh1,
    float* __restrict__ h2_new, float* __restrict__ enc_tm1,
    int l0_active, int l1_active)
{
    __shared__ float sA[2 * 1088];     // 8704 B
    __shared__ float sW[6 * 16 * 36];  // 13824 B
    if (blockIdx.z == 0) {
        if (!l0_active) return;
        gru_fused_tile(sA, sW, gi0, Whh0, bhh0, h1_old, h1_new, seqA_t,
                       blockIdx.x, blockIdx.y);
    } else {
        if (!l1_active) return;
        gru_dual_tile(sA, sW, x1, Wih1, bih1, h2_old, Whh1, bhh1,
                      h2_new, enc_tm1, nullptr, blockIdx.x, blockIdx.y);
    }
}

// Decoder wrappers (grid (32,4) x 512)
__global__ void __launch_bounds__(512) gru_step_k(
    const float* __restrict__ gi, const float* __restrict__ Whh,
    const float* __restrict__ bhh, const float* __restrict__ h_old,
    float* __restrict__ h_new)
{
    __shared__ float sA[2 * 1088];
    __shared__ float sW[6 * 16 * 36];
    gru_fused_tile(sA, sW, gi, Whh, bhh, h_old, h_new, nullptr,
                   blockIdx.x, blockIdx.y);
}
__global__ void __launch_bounds__(512) gru_dual_k(
    const float* __restrict__ x,   const float* __restrict__ Wih,
    const float* __restrict__ bih, const float* __restrict__ h_old,
    const float* __restrict__ Whh, const float* __restrict__ bhh,
    float* __restrict__ h_new,     float* __restrict__ cat_out)
{
    __shared__ float sA[2 * 1088];
    __shared__ float sW[6 * 16 * 36];
    gru_dual_tile(sA, sW, x, Wih, bih, h_old, Whh, bhh,
                  h_new, nullptr, cat_out, blockIdx.x, blockIdx.y);
}

// ---------------------------------------------------------------------------
// Embedding gather: g_A0[(t*B+b)*E + e] = emb[x[b,t]][e]
// ---------------------------------------------------------------------------
__global__ void gather_emb(const float* __restrict__ emb, const int* __restrict__ x)
{
    int idx = blockIdx.x * blockDim.x + threadIdx.x;  // over T*B*E/4
    int col = idx & (kE / 4 - 1);
    int row = idx >> 7;            // E/4 = 128
    int t = row >> 8;              // /kB
    int b = row & (kB - 1);
    int tok = x[b * kTin + t];
    ((float4*)g_A0)[idx] = ((const float4*)emb)[(size_t)tok * (kE / 4) + col];
}

// ---------------------------------------------------------------------------
// Teacher-forcing shift: ys_in[t,b,:] = (t==0) ? 0 : y[b,t-1,:]
// ---------------------------------------------------------------------------
__global__ void build_ysin(const float* __restrict__ y)
{
    int idx = blockIdx.x * blockDim.x + threadIdx.x;  // over Tout*B*Y/4
    int col = idx & (kY / 4 - 1);
    int row = idx >> 8;            // Y/4 = 256
    int t = row >> 8;              // /kB
    int b = row & (kB - 1);
    float4 v = make_float4(0.f, 0.f, 0.f, 0.f);
    if (t > 0) v = ((const float4*)y)[((size_t)b * kTout + (t - 1)) * (kY / 4) + col];
    ((float4*)g_ysin)[idx] = v;
}

__global__ void zero_state()
{
    int i = blockIdx.x * blockDim.x + threadIdx.x;
    g_h1[0][i] = 0.f; g_h2[0][i] = 0.f;
}

// ---------------------------------------------------------------------------
// y.sum() : deterministic two-stage reduction
// ---------------------------------------------------------------------------
__global__ void ysum_part(const float* __restrict__ y)
{
    __shared__ float red[8];
    int blk = blockIdx.x, tid = threadIdx.x;
    const float* p = y + (size_t)blk * 1024;
    float s = p[tid] + p[tid + 256] + p[tid + 512] + p[tid + 768];
    s = block_sum(s, red);
    if (tid == 0) g_ypart[blk] = s;
}
__global__ void ysum_final()
{
    __shared__ float red[8];
    int tid = threadIdx.x;
    float s = 0.f;
    for (int i = tid; i < kTout * kB; i += 256) s += g_ypart[i];
    s = block_sum(s, red);
    if (tid == 0) g_ysum = s;
}

// ---------------------------------------------------------------------------
// Attention (per decoder step): one block per batch row.
// ---------------------------------------------------------------------------
__global__ void attn_kernel(const float* __restrict__ h2)
{
    __shared__ float sh[kH];
    __shared__ float sc[kTin];
    __shared__ float red[16];
    int b = blockIdx.x, tid = threadIdx.x;
    int w = tid >> 5, l = tid & 31;

#pragma unroll
    for (int q = 0; q < 4; q++) sh[tid + 256 * q] = h2[b * kH + tid + 256 * q];
    __syncthreads();

    for (int si = 0; si < 32; si++) {
        int s = w * 32 + si;
        const float* row = g_enc + ((size_t)s * kB + b) * kH;
        float acc = 0.f;
#pragma unroll 8
        for (int k = 0; k < 32; k++) acc += row[l + 32 * k] * sh[l + 32 * k];
        acc = warp_sum(acc);
        if (l == 0) sc[s] = acc;
    }
    __syncthreads();

    float v = sc[tid];
    float m = warp_max(v);
    if (l == 0) red[w] = m;
    __syncthreads();
    float bm = red[0];
#pragma unroll
    for (int i = 1; i < 8; i++) bm = fmaxf(bm, red[i]);
    float p = expf(v - bm);
    sc[tid] = p;
    float ps = warp_sum(p);
    if (l == 0) red[8 + w] = ps;
    __syncthreads();
    float tot = 0.f;
#pragma unroll
    for (int i = 0; i < 8; i++) tot += red[8 + i];

    float a0 = 0.f, a1 = 0.f, a2 = 0.f, a3 = 0.f;
#pragma unroll 4
    for (int s = 0; s < kTin; s++) {
        float pr = sc[s];
        const float* row = g_enc + ((size_t)s * kB + b) * kH;
        a0 += pr * row[tid];       a1 += pr * row[tid + 256];
        a2 += pr * row[tid + 512]; a3 += pr * row[tid + 768];
    }
    float inv = 1.0f / tot;
    float* cb = g_cat + b * 2 * kH;
    cb[tid] = a0 * inv; cb[tid + 256] = a1 * inv;
    cb[tid + 512] = a2 * inv; cb[tid + 768] = a3 * inv;
}

// ---------------------------------------------------------------------------
// Per-step NLL: loss[t,b] = sum_v y[b,t,v] * (lse(logits[b,:]) - logits[b,v])
// ---------------------------------------------------------------------------
__global__ void loss_kernel(const float* __restrict__ y, int t)
{
    __shared__ float red[8];
    int b = blockIdx.x, tid = threadIdx.x;
    const float* lr = g_logits + b * kY;
    float l0 = lr[tid], l1 = lr[tid + 256], l2 = lr[tid + 512], l3 = lr[tid + 768];
    float m = block_max(fmaxf(fmaxf(l0, l1), fmaxf(l2, l3)), red);
    float se = block_sum(expf(l0 - m) + expf(l1 - m) + expf(l2 - m) + expf(l3 - m), red);
    float lse = m + logf(se);
    const float* yr = y + ((size_t)b * kTout + t) * kY;
    float a = yr[tid] * (lse - l0) + yr[tid + 256] * (lse - l1)
            + yr[tid + 512] * (lse - l2) + yr[tid + 768] * (lse - l3);
    a = block_sum(a, red);
    if (tid == 0) g_loss[t * kB + b] = a;
}

__global__ void final_kernel(float* __restrict__ out)
{
    __shared__ float red[8];
    int tid = threadIdx.x;
    float s = 0.f;
    for (int i = tid; i < kTout * kB; i += 256) s += g_loss[i];
    s = block_sum(s, red);
    if (tid == 0) out[0] = s / g_ysum;
}

// ---------------------------------------------------------------------------
// Orchestration
// ---------------------------------------------------------------------------
extern "C" void kernel_launch(void* const* d_in, const int* in_sizes, int n_in,
                              void* d_out, int out_size)
{
    const int*   x    = (const int*)d_in[0];
    const float* y    = (const float*)d_in[1];
    const float* emb  = (const float*)d_in[2];
    const float* eWih0 = (const float*)d_in[3],  *eWhh0 = (const float*)d_in[4];
    const float* ebih0 = (const float*)d_in[5],  *ebhh0 = (const float*)d_in[6];
    const float* eWih1 = (const float*)d_in[7],  *eWhh1 = (const float*)d_in[8];
    const float* ebih1 = (const float*)d_in[9],  *ebhh1 = (const float*)d_in[10];
    const float* dWih0 = (const float*)d_in[11], *dWhh0 = (const float*)d_in[12];
    const float* dbih0 = (const float*)d_in[13], *dbhh0 = (const float*)d_in[14];
    const float* dWih1 = (const float*)d_in[15], *dWhh1 = (const float*)d_in[16];
    const float* dbih1 = (const float*)d_in[17], *dbhh1 = (const float*)d_in[18];
    const float* mapW  = (const float*)d_in[19], *mapb  = (const float*)d_in[20];
    float* out = (float*)d_out;

    float *pA0, *pgi, *pseqA, *penc, *pdgi, *pysin, *ph1, *ph2, *pcat, *plogits;
    cudaGetSymbolAddress((void**)&pA0, g_A0);
    cudaGetSymbolAddress((void**)&pgi, g_gi);
    cudaGetSymbolAddress((void**)&pseqA, g_seqA);
    cudaGetSymbolAddress((void**)&penc, g_enc);
    cudaGetSymbolAddress((void**)&pdgi, g_dgi);
    cudaGetSymbolAddress((void**)&pysin, g_ysin);
    cudaGetSymbolAddress((void**)&ph1, g_h1);
    cudaGetSymbolAddress((void**)&ph2, g_h2);
    cudaGetSymbolAddress((void**)&pcat, g_cat);
    cudaGetSymbolAddress((void**)&plogits, g_logits);

    float* h1buf[2] = { ph1, ph1 + (size_t)kB * kH };
    float* h2buf[2] = { ph2, ph2 + (size_t)kB * kH };

    const dim3 gBig(kH3 / 64, kTin * kB / 64);   // enc L0 input gates
    const dim3 gDec(kH3 / 64, kTout * kB / 64);  // dec L0 input gates
    const dim3 gMap(kY / 64, kB / 64);
    const dim3 gPair(kH / 32, kB / 64, 2);       // 32 x 4 x 2 = 256 blocks
    const dim3 gStep(kH / 32, kB / 64);          // 32 x 4

    // ---- prologue (ordered so ncu -s5 lands on a pair step) ----
    zero_state<<<kB * kH / 256, 256>>>();                              // #1
    gather_emb<<<(kTin * kB * kE / 4) / 256, 256>>>(emb, x);           // #2
    gemm_nt<<<gBig, 256>>>(pA0, eWih0, ebih0, pgi, kTin * kB, kH3, kE);// #3

    // ---- pipelined encoder: L0 step t  ||  L1 step t-1 ----
    int p1 = 0, p2 = 0;
    for (int t = 0; t <= kTin; t++) {                                   // #4..#260
        int l0 = (t < kTin) ? 1 : 0;
        int l1 = (t >= 1) ? 1 : 0;
        enc_pair<<<gPair, 512>>>(
            pgi + (size_t)t * kB * kH3, eWhh0, ebhh0,
            h1buf[p1], h1buf[p1 ^ 1], pseqA + (size_t)t * kB * kH,
            pseqA + (size_t)(t - 1) * kB * kH, eWih1, ebih1,
            h2buf[p2], eWhh1, ebhh1,
            h2buf[p2 ^ 1], penc + (size_t)(t - 1) * kB * kH,
            l0, l1);
        if (l0) p1 ^= 1;
        if (l1) p2 ^= 1;
    }
    // h1buf[p1] = enc L0 final hidden; h2buf[p2] = enc L1 final hidden.

    // ---- decoder prep ----
    build_ysin<<<(kTout * kB * kY / 4) / 256, 256>>>(y);
    gemm_nt<<<gDec, 256>>>(pysin, dWih0, dbih0, pdgi, kTout * kB, kH3, kY);

    // ---- decoder ----
    for (int t = 0; t < kTout; t++) {
        gru_step_k<<<gStep, 512>>>(pdgi + (size_t)t * kB * kH3, dWhh0, dbhh0,
                                   h1buf[p1], h1buf[p1 ^ 1]);
        p1 ^= 1;
        gru_dual_k<<<gStep, 512>>>(h1buf[p1], dWih1, dbih1,
                                   h2buf[p2], dWhh1, dbhh1,
                                   h2buf[p2 ^ 1], pcat + kH);
        p2 ^= 1;
        attn_kernel<<<kB, 256>>>(h2buf[p2]);
        gemm_nt<<<gMap, 256>>>(pcat, mapW, mapb, plogits, kB, kY, 2 * kH);
        loss_kernel<<<kB, 256>>>(y, t);
    }

    // ---- epilogue reductions ----
    ysum_part<<<kTout * kB, 256>>>(y);
    ysum_final<<<1, 256>>>();
    final_kernel<<<1, 256>>>(out);
}

// round 14
// speedup vs baseline: 2.1578x; 2.0913x over previous
#include <cuda_runtime.h>
#include <cstdint>
#include <cstddef>

// ---------------------------------------------------------------------------
// Problem constants (fixed by the reference)
// ---------------------------------------------------------------------------
namespace {
constexpr int kB    = 256;    // batch
constexpr int kTin  = 256;    // encoder steps
constexpr int kTout = 32;     // decoder steps
constexpr int kE    = 512;    // embedding dim
constexpr int kH    = 1024;   // hidden dim
constexpr int kY    = 1024;   // output feature dim
constexpr int kH3   = 3 * kH; // GRU gate width
}

// ---------------------------------------------------------------------------
// Scratch (device globals -- allocation-free rule)
// ---------------------------------------------------------------------------
__device__ float g_A0[(size_t)kTin * kB * kE];      // gathered embeddings  [T*B, E]
__device__ float g_gi[(size_t)kTin * kB * kH3];     // batched input gates  [T*B, 3H]
__device__ float g_seqA[(size_t)kTin * kB * kH];    // encoder layer0 outputs
__device__ float g_enc[(size_t)kTin * kB * kH];     // encoder layer1 outputs (enc_out)
__device__ float g_dgi[(size_t)kTout * kB * kH3];   // decoder L0 batched input gates
__device__ float g_ysin[(size_t)kTout * kB * kY];   // shifted teacher inputs
__device__ float g_h1[2][kB * kH];                  // ping-pong hidden (layer-A role)
__device__ float g_h2[2][kB * kH];                  // ping-pong hidden (layer-B role)
__device__ float g_cat[kB * 2 * kH];                // [attn | h2]
__device__ float g_logits[kB * kY];
__device__ float g_loss[kTout * kB];
__device__ float g_ypart[kTout * kB];
__device__ float g_ysum;

// ---------------------------------------------------------------------------
// Reduction helpers (blockDim.x == 256 assumed)
// ---------------------------------------------------------------------------
__device__ __forceinline__ float warp_sum(float v) {
#pragma unroll
    for (int o = 16; o; o >>= 1) v += __shfl_xor_sync(0xffffffffu, v, o);
    return v;
}
__device__ __forceinline__ float warp_max(float v) {
#pragma unroll
    for (int o = 16; o; o >>= 1) v = fmaxf(v, __shfl_xor_sync(0xffffffffu, v, o));
    return v;
}
__device__ __forceinline__ float block_sum(float v, float* red) {
    int l = threadIdx.x & 31, w = threadIdx.x >> 5;
    v = warp_sum(v);
    if (l == 0) red[w] = v;
    __syncthreads();
    float s = 0.f;
#pragma unroll
    for (int i = 0; i < 8; i++) s += red[i];
    __syncthreads();
    return s;
}
__device__ __forceinline__ float block_max(float v, float* red) {
    int l = threadIdx.x & 31, w = threadIdx.x >> 5;
    v = warp_max(v);
    if (l == 0) red[w] = v;
    __syncthreads();
    float s = red[0];
#pragma unroll
    for (int i = 1; i < 8; i++) s = fmaxf(s, red[i]);
    __syncthreads();
    return s;
}
__device__ __forceinline__ float sigmoidf(float x) { return 1.0f / (1.0f + expf(-x)); }

// ---------------------------------------------------------------------------
// gemm_nt128:  C[M,N] = A[M,K] * W[N,K]^T (+bias)
// 128x128x8 tile, 256 threads, 8x8 microtile => 64 FMA / 64 smem-bytes per k.
// M%128==0, N%128==0, K%8==0 (all call sites satisfy this).
// ---------------------------------------------------------------------------
__global__ void __launch_bounds__(256) gemm_nt128(
    const float* __restrict__ A, const float* __restrict__ W,
    const float* __restrict__ bias, float* __restrict__ C,
    int M, int N, int K)
{
    __shared__ float sA[8 * 132];
    __shared__ float sW[8 * 132];

    const int tid = threadIdx.x;
    const int tx = tid & 15, ty = tid >> 4;          // 16 x 16 thread grid
    const int m0 = blockIdx.y * 128, n0 = blockIdx.x * 128;
    const int lrow = tid >> 1;                       // 0..127
    const int lk   = (tid & 1) * 4;                  // 0 or 4

    const float* Ap = A + (size_t)(m0 + lrow) * K + lk;
    const float* Wp = W + (size_t)(n0 + lrow) * K + lk;

    float acc[8][8] = {};
    for (int k0 = 0; k0 < K; k0 += 8) {
        float4 av = *(const float4*)(Ap + k0);
        float4 wv = *(const float4*)(Wp + k0);
        sA[(lk + 0) * 132 + lrow] = av.x; sA[(lk + 1) * 132 + lrow] = av.y;
        sA[(lk + 2) * 132 + lrow] = av.z; sA[(lk + 3) * 132 + lrow] = av.w;
        sW[(lk + 0) * 132 + lrow] = wv.x; sW[(lk + 1) * 132 + lrow] = wv.y;
        sW[(lk + 2) * 132 + lrow] = wv.z; sW[(lk + 3) * 132 + lrow] = wv.w;
        __syncthreads();
#pragma unroll
        for (int kk = 0; kk < 8; kk++) {
            float a[8], w[8];
            *(float4*)&a[0] = *(const float4*)&sA[kk * 132 + ty * 8];
            *(float4*)&a[4] = *(const float4*)&sA[kk * 132 + ty * 8 + 4];
            *(float4*)&w[0] = *(const float4*)&sW[kk * 132 + tx * 8];
            *(float4*)&w[4] = *(const float4*)&sW[kk * 132 + tx * 8 + 4];
#pragma unroll
            for (int i = 0; i < 8; i++)
#pragma unroll
                for (int j = 0; j < 8; j++)
                    acc[i][j] += a[i] * w[j];
        }
        __syncthreads();
    }

    float bv[8] = {};
    if (bias) {
        *(float4*)&bv[0] = *(const float4*)(bias + n0 + tx * 8);
        *(float4*)&bv[4] = *(const float4*)(bias + n0 + tx * 8 + 4);
    }
#pragma unroll
    for (int i = 0; i < 8; i++) {
        float4 o0, o1;
        o0.x = acc[i][0] + bv[0]; o0.y = acc[i][1] + bv[1];
        o0.z = acc[i][2] + bv[2]; o0.w = acc[i][3] + bv[3];
        o1.x = acc[i][4] + bv[4]; o1.y = acc[i][5] + bv[5];
        o1.z = acc[i][6] + bv[6]; o1.w = acc[i][7] + bv[7];
        float* cp = C + (size_t)(m0 + ty * 8 + i) * N + n0 + tx * 8;
        *(float4*)cp = o0;
        *(float4*)(cp + 4) = o1;
    }
}

// ---------------------------------------------------------------------------
// gemm_nt64: old 64x64x16 kernel, kept for the small mapping GEMM only.
// ---------------------------------------------------------------------------
__global__ void __launch_bounds__(256) gemm_nt64(
    const float* __restrict__ A, const float* __restrict__ W,
    const float* __restrict__ bias, float* __restrict__ C,
    int M, int N, int K)
{
    constexpr int BK = 16;
    __shared__ float As[BK][68];
    __shared__ float Ws[BK][68];

    const int tid = threadIdx.x;
    const int tx = tid & 15, ty = tid >> 4;
    const int m0 = blockIdx.y * 64, n0 = blockIdx.x * 64;
    const int lrow = tid >> 2;
    const int lk   = (tid & 3) * 4;

    const float* Aptr = A + (size_t)(m0 + lrow) * K + lk;
    const float* Wptr = W + (size_t)(n0 + lrow) * K + lk;

    float acc[4][4] = {};
    for (int k0 = 0; k0 < K; k0 += BK) {
        float4 av = *(const float4*)(Aptr + k0);
        float4 wv = *(const float4*)(Wptr + k0);
        As[lk + 0][lrow] = av.x; As[lk + 1][lrow] = av.y;
        As[lk + 2][lrow] = av.z; As[lk + 3][lrow] = av.w;
        Ws[lk + 0][lrow] = wv.x; Ws[lk + 1][lrow] = wv.y;
        Ws[lk + 2][lrow] = wv.z; Ws[lk + 3][lrow] = wv.w;
        __syncthreads();
#pragma unroll
        for (int k = 0; k < BK; k++) {
            float4 a = *(const float4*)&As[k][ty * 4];
            float4 b = *(const float4*)&Ws[k][tx * 4];
            const float* af = (const float*)&a;
            const float* bf = (const float*)&b;
#pragma unroll
            for (int i = 0; i < 4; i++)
#pragma unroll
                for (int j = 0; j < 4; j++)
                    acc[i][j] += af[i] * bf[j];
        }
        __syncthreads();
    }

    float4 bvv = make_float4(0.f, 0.f, 0.f, 0.f);
    if (bias) bvv = *(const float4*)(bias + n0 + tx * 4);
#pragma unroll
    for (int i = 0; i < 4; i++) {
        float4 o;
        o.x = acc[i][0] + bvv.x; o.y = acc[i][1] + bvv.y;
        o.z = acc[i][2] + bvv.z; o.w = acc[i][3] + bvv.w;
        *(float4*)(C + (size_t)(m0 + ty * 4 + i) * N + n0 + tx * 4) = o;
    }
}

// ---------------------------------------------------------------------------
// gru_step2: fused recurrent GRU step, 256 threads, 2-way K-split.
//   Block tile: 64 batch rows x 32 hidden cols x 3 gates.  Grid (32,4).
//   Thread (within 128-thread K-group): 4 rows x (3 gates x 4 cols) = 48 acc.
//   Group kg processes K half [kg*512, kg*512+512); group 1 dumps partials
//   to smem; group 0 reduces and runs the gate epilogue.
//   gi has bih folded in (batched GEMM); bhh added here.
// ---------------------------------------------------------------------------
__global__ void __launch_bounds__(256) gru_step2(
    const float* __restrict__ gi, const float* __restrict__ Whh,
    const float* __restrict__ bhh, const float* __restrict__ h_old,
    float* __restrict__ h_new, float* __restrict__ seq_out)
{
    // staging: sA = S[0..2175] ([2][16][68]), sW = S[2176..5631] ([2][3][16][36])
    // reduction buffer reuses S[0..6143] after the K loop.
    __shared__ float S[6144];
    float* sA = S;
    float* sW = S + 2176;

    const int tid = threadIdx.x;
    const int kg  = tid >> 7;            // K-group 0/1
    const int t   = tid & 127;
    const int tyg = t >> 3;              // 0..15 -> rows tyg*4..+3
    const int txg = t & 7;               // 0..7  -> cols txg*4..+3
    const int m0 = blockIdx.y * 64, n0 = blockIdx.x * 32;

    float acc[3][4][4] = {};

    for (int k0 = 0; k0 < 512; k0 += 16) {
        // stage A: 2 halves x 64 rows x 4 k-quads = 512 float4; 2 per thread
#pragma unroll
        for (int i = tid; i < 512; i += 256) {
            int g = i >> 8, rem = i & 255;
            int row = rem >> 2, kq = (rem & 3) * 4;
            float4 v = *(const float4*)(h_old + (size_t)(m0 + row) * kH + g * 512 + k0 + kq);
            float* d = sA + g * 1088;
            d[(kq + 0) * 68 + row] = v.x; d[(kq + 1) * 68 + row] = v.y;
            d[(kq + 2) * 68 + row] = v.z; d[(kq + 3) * 68 + row] = v.w;
        }
        // stage W: 2 halves x 3 gates x 32 w-rows x 4 k-quads = 768 float4; 3/thread
#pragma unroll
        for (int i = tid; i < 768; i += 256) {
            int g = (i >= 384) ? 1 : 0;
            int rem = i - g * 384;
            int gate = rem >> 7;
            int r2 = rem & 127;
            int rr = r2 >> 2, kq = (r2 & 3) * 4;
            float4 v = *(const float4*)(Whh + (size_t)(gate * kH + n0 + rr) * kH + g * 512 + k0 + kq);
            float* d = sW + (g * 3 + gate) * 576;
            d[(kq + 0) * 36 + rr] = v.x; d[(kq + 1) * 36 + rr] = v.y;
            d[(kq + 2) * 36 + rr] = v.z; d[(kq + 3) * 36 + rr] = v.w;
        }
        __syncthreads();
        const float* mA = sA + kg * 1088;
        const float* mW = sW + kg * 3 * 576;
#pragma unroll
        for (int kk = 0; kk < 16; kk++) {
            float a[4];
            *(float4*)a = *(const float4*)&mA[kk * 68 + tyg * 4];
#pragma unroll
            for (int gt = 0; gt < 3; gt++) {
                float w[4];
                *(float4*)w = *(const float4*)&mW[gt * 576 + kk * 36 + txg * 4];
#pragma unroll
                for (int r = 0; r < 4; r++)
#pragma unroll
                    for (int c = 0; c < 4; c++)
                        acc[gt][r][c] += a[r] * w[c];
            }
        }
        __syncthreads();
    }

    // K-split combine (staging smem is dead now; reuse as reduction buffer)
    if (kg == 1) {
        float* d = S + t * 48;
#pragma unroll
        for (int gt = 0; gt < 3; gt++)
#pragma unroll
            for (int r = 0; r < 4; r++)
#pragma unroll
                for (int c = 0; c < 4; c++)
                    d[gt * 16 + r * 4 + c] = acc[gt][r][c];
    }
    __syncthreads();
    if (kg == 0) {
        const float* d = S + t * 48;
#pragma unroll
        for (int gt = 0; gt < 3; gt++)
#pragma unroll
            for (int r = 0; r < 4; r++)
#pragma unroll
                for (int c = 0; c < 4; c++)
                    acc[gt][r][c] += d[gt * 16 + r * 4 + c];

        const int j = n0 + txg * 4;
        float br[4], bz[4], bn[4];
        *(float4*)br = *(const float4*)(bhh + j);
        *(float4*)bz = *(const float4*)(bhh + kH + j);
        *(float4*)bn = *(const float4*)(bhh + 2 * kH + j);
#pragma unroll
        for (int r = 0; r < 4; r++) {
            const int b = m0 + tyg * 4 + r;
            const float* gib = gi + (size_t)b * kH3;
            float gr[4], gz[4], gn[4], hv[4], o[4];
            *(float4*)gr = *(const float4*)(gib + j);
            *(float4*)gz = *(const float4*)(gib + kH + j);
            *(float4*)gn = *(const float4*)(gib + 2 * kH + j);
            *(float4*)hv = *(const float4*)(h_old + (size_t)b * kH + j);
#pragma unroll
            for (int c = 0; c < 4; c++) {
                float rr = sigmoidf(gr[c] + acc[0][r][c] + br[c]);
                float zz = sigmoidf(gz[c] + acc[1][r][c] + bz[c]);
                float nn = tanhf(gn[c] + rr * (acc[2][r][c] + bn[c]));
                o[c] = (1.0f - zz) * nn + zz * hv[c];
            }
            *(float4*)(h_new + (size_t)b * kH + j) = *(float4*)o;
            if (seq_out) *(float4*)(seq_out + (size_t)b * kH + j) = *(float4*)o;
        }
    }
}

// ---------------------------------------------------------------------------
// 512-thread dual-GEMM GRU step (decoder layer 1 only):
//   gi = x @ Wih^T + bih,  gh = h_old @ Whh^T + bhh  (6 slabs in-register)
//   h_new = (1-z)*n + z*h_old ; also writes cat_out[b*2H + j] = h_new
// ---------------------------------------------------------------------------
__global__ void __launch_bounds__(512) gru_dual_k(
    const float* __restrict__ x,   const float* __restrict__ Wih,
    const float* __restrict__ bih, const float* __restrict__ h_old,
    const float* __restrict__ Whh, const float* __restrict__ bhh,
    float* __restrict__ h_new,     float* __restrict__ cat_out)
{
    __shared__ float sA[2 * 1088];     // [2][16][68]
    __shared__ float sW[6 * 16 * 36];  // [6][16][36]

    const int tid = threadIdx.x;
    const int m0 = blockIdx.y * 64, n0 = blockIdx.x * 32;
    const int tx = tid & 7, ty = tid >> 3;

    float acc[6][4] = {};
    for (int k0 = 0; k0 < kH; k0 += 16) {
        {
            int buf = tid >> 8, rr = (tid >> 2) & 63, kk = (tid & 3) * 4;
            const float* src = buf ? h_old : x;
            float4 av = *(const float4*)(src + (size_t)(m0 + rr) * kH + k0 + kk);
            float* dst = sA + buf * 1088;
            dst[(kk + 0) * 68 + rr] = av.x; dst[(kk + 1) * 68 + rr] = av.y;
            dst[(kk + 2) * 68 + rr] = av.z; dst[(kk + 3) * 68 + rr] = av.w;
        }
        for (int i = tid; i < 768; i += 512) {
            int s = i >> 7, rr = (i >> 2) & 31, kk = (i & 3) * 4;
            const float* Wsrc = (s < 3) ? Wih : Whh;
            int g = (s < 3) ? s : s - 3;
            float4 wv = *(const float4*)(Wsrc + (size_t)(g * kH + n0 + rr) * kH + k0 + kk);
            sW[(s * 16 + kk + 0) * 36 + rr] = wv.x; sW[(s * 16 + kk + 1) * 36 + rr] = wv.y;
            sW[(s * 16 + kk + 2) * 36 + rr] = wv.z; sW[(s * 16 + kk + 3) * 36 + rr] = wv.w;
        }
        __syncthreads();
#pragma unroll
        for (int k = 0; k < 16; k++) {
            float ax = sA[k * 68 + ty];
            float ah = sA[1088 + k * 68 + ty];
#pragma unroll
            for (int s = 0; s < 6; s++) {
                float4 w = *(const float4*)&sW[(s * 16 + k) * 36 + tx * 4];
                float a = (s < 3) ? ax : ah;
                acc[s][0] += a * w.x; acc[s][1] += a * w.y;
                acc[s][2] += a * w.z; acc[s][3] += a * w.w;
            }
        }
        __syncthreads();
    }

    const int j = n0 + tx * 4;
    const float4 bir = *(const float4*)(bih + j);
    const float4 biz = *(const float4*)(bih + kH + j);
    const float4 bin = *(const float4*)(bih + 2 * kH + j);
    const float4 bhr = *(const float4*)(bhh + j);
    const float4 bhz = *(const float4*)(bhh + kH + j);
    const float4 bhn = *(const float4*)(bhh + 2 * kH + j);
    float4 hv = *(const float4*)(h_old + (size_t)(m0 + ty) * kH + j);
    float4 o;
    float* op = (float*)&o;
    const float* hvp = (const float*)&hv;
    const float* birp = (const float*)&bir; const float* bizp = (const float*)&biz;
    const float* binp = (const float*)&bin; const float* bhrp = (const float*)&bhr;
    const float* bhzp = (const float*)&bhz; const float* bhnp = (const float*)&bhn;
#pragma unroll
    for (int c = 0; c < 4; c++) {
        float r = sigmoidf(acc[0][c] + birp[c] + acc[3][c] + bhrp[c]);
        float z = sigmoidf(acc[1][c] + bizp[c] + acc[4][c] + bhzp[c]);
        float n = tanhf(acc[2][c] + binp[c] + r * (acc[5][c] + bhnp[c]));
        op[c] = (1.0f - z) * n + z * hvp[c];
    }
    const int b = m0 + ty;
    *(float4*)(h_new + (size_t)b * kH + j) = o;
    *(float4*)(cat_out + (size_t)b * 2 * kH + j) = o;
}

// ---------------------------------------------------------------------------
// Embedding gather / teacher shift / init / reductions
// ---------------------------------------------------------------------------
__global__ void gather_emb(const float* __restrict__ emb, const int* __restrict__ x)
{
    int idx = blockIdx.x * blockDim.x + threadIdx.x;
    int col = idx & (kE / 4 - 1);
    int row = idx >> 7;
    int t = row >> 8;
    int b = row & (kB - 1);
    int tok = x[b * kTin + t];
    ((float4*)g_A0)[idx] = ((const float4*)emb)[(size_t)tok * (kE / 4) + col];
}

__global__ void build_ysin(const float* __restrict__ y)
{
    int idx = blockIdx.x * blockDim.x + threadIdx.x;
    int col = idx & (kY / 4 - 1);
    int row = idx >> 8;
    int t = row >> 8;
    int b = row & (kB - 1);
    float4 v = make_float4(0.f, 0.f, 0.f, 0.f);
    if (t > 0) v = ((const float4*)y)[((size_t)b * kTout + (t - 1)) * (kY / 4) + col];
    ((float4*)g_ysin)[idx] = v;
}

__global__ void zero_state()
{
    int i = blockIdx.x * blockDim.x + threadIdx.x;
    g_h1[0][i] = 0.f; g_h2[0][i] = 0.f;
}

__global__ void ysum_part(const float* __restrict__ y)
{
    __shared__ float red[8];
    int blk = blockIdx.x, tid = threadIdx.x;
    const float* p = y + (size_t)blk * 1024;
    float s = p[tid] + p[tid + 256] + p[tid + 512] + p[tid + 768];
    s = block_sum(s, red);
    if (tid == 0) g_ypart[blk] = s;
}
__global__ void ysum_final()
{
    __shared__ float red[8];
    int tid = threadIdx.x;
    float s = 0.f;
    for (int i = tid; i < kTout * kB; i += 256) s += g_ypart[i];
    s = block_sum(s, red);
    if (tid == 0) g_ysum = s;
}

// ---------------------------------------------------------------------------
// Attention: one block per batch row.
// ---------------------------------------------------------------------------
__global__ void attn_kernel(const float* __restrict__ h2)
{
    __shared__ float sh[kH];
    __shared__ float sc[kTin];
    __shared__ float red[16];
    int b = blockIdx.x, tid = threadIdx.x;
    int w = tid >> 5, l = tid & 31;

#pragma unroll
    for (int q = 0; q < 4; q++) sh[tid + 256 * q] = h2[b * kH + tid + 256 * q];
    __syncthreads();

    for (int si = 0; si < 32; si++) {
        int s = w * 32 + si;
        const float* row = g_enc + ((size_t)s * kB + b) * kH;
        float acc = 0.f;
#pragma unroll 8
        for (int k = 0; k < 32; k++) acc += row[l + 32 * k] * sh[l + 32 * k];
        acc = warp_sum(acc);
        if (l == 0) sc[s] = acc;
    }
    __syncthreads();

    float v = sc[tid];
    float m = warp_max(v);
    if (l == 0) red[w] = m;
    __syncthreads();
    float bm = red[0];
#pragma unroll
    for (int i = 1; i < 8; i++) bm = fmaxf(bm, red[i]);
    float p = expf(v - bm);
    sc[tid] = p;
    float ps = warp_sum(p);
    if (l == 0) red[8 + w] = ps;
    __syncthreads();
    float tot = 0.f;
#pragma unroll
    for (int i = 0; i < 8; i++) tot += red[8 + i];

    float a0 = 0.f, a1 = 0.f, a2 = 0.f, a3 = 0.f;
#pragma unroll 4
    for (int s = 0; s < kTin; s++) {
        float pr = sc[s];
        const float* row = g_enc + ((size_t)s * kB + b) * kH;
        a0 += pr * row[tid];       a1 += pr * row[tid + 256];
        a2 += pr * row[tid + 512]; a3 += pr * row[tid + 768];
    }
    float inv = 1.0f / tot;
    float* cb = g_cat + b * 2 * kH;
    cb[tid] = a0 * inv; cb[tid + 256] = a1 * inv;
    cb[tid + 512] = a2 * inv; cb[tid + 768] = a3 * inv;
}

// ---------------------------------------------------------------------------
// Per-step NLL + final
// ---------------------------------------------------------------------------
__global__ void loss_kernel(const float* __restrict__ y, int t)
{
    __shared__ float red[8];
    int b = blockIdx.x, tid = threadIdx.x;
    const float* lr = g_logits + b * kY;
    float l0 = lr[tid], l1 = lr[tid + 256], l2 = lr[tid + 512], l3 = lr[tid + 768];
    float m = block_max(fmaxf(fmaxf(l0, l1), fmaxf(l2, l3)), red);
    float se = block_sum(expf(l0 - m) + expf(l1 - m) + expf(l2 - m) + expf(l3 - m), red);
    float lse = m + logf(se);
    const float* yr = y + ((size_t)b * kTout + t) * kY;
    float a = yr[tid] * (lse - l0) + yr[tid + 256] * (lse - l1)
            + yr[tid + 512] * (lse - l2) + yr[tid + 768] * (lse - l3);
    a = block_sum(a, red);
    if (tid == 0) g_loss[t * kB + b] = a;
}

__global__ void final_kernel(float* __restrict__ out)
{
    __shared__ float red[8];
    int tid = threadIdx.x;
    float s = 0.f;
    for (int i = tid; i < kTout * kB; i += 256) s += g_loss[i];
    s = block_sum(s, red);
    if (tid == 0) out[0] = s / g_ysum;
}

// ---------------------------------------------------------------------------
// Orchestration
// ---------------------------------------------------------------------------
extern "C" void kernel_launch(void* const* d_in, const int* in_sizes, int n_in,
                              void* d_out, int out_size)
{
    const int*   x    = (const int*)d_in[0];
    const float* y    = (const float*)d_in[1];
    const float* emb  = (const float*)d_in[2];
    const float* eWih0 = (const float*)d_in[3],  *eWhh0 = (const float*)d_in[4];
    const float* ebih0 = (const float*)d_in[5],  *ebhh0 = (const float*)d_in[6];
    const float* eWih1 = (const float*)d_in[7],  *eWhh1 = (const float*)d_in[8];
    const float* ebih1 = (const float*)d_in[9],  *ebhh1 = (const float*)d_in[10];
    const float* dWih0 = (const float*)d_in[11], *dWhh0 = (const float*)d_in[12];
    const float* dbih0 = (const float*)d_in[13], *dbhh0 = (const float*)d_in[14];
    const float* dWih1 = (const float*)d_in[15], *dWhh1 = (const float*)d_in[16];
    const float* dbih1 = (const float*)d_in[17], *dbhh1 = (const float*)d_in[18];
    const float* mapW  = (const float*)d_in[19], *mapb  = (const float*)d_in[20];
    float* out = (float*)d_out;

    float *pA0, *pgi, *pseqA, *penc, *pdgi, *pysin, *ph1, *ph2, *pcat, *plogits;
    cudaGetSymbolAddress((void**)&pA0, g_A0);
    cudaGetSymbolAddress((void**)&pgi, g_gi);
    cudaGetSymbolAddress((void**)&pseqA, g_seqA);
    cudaGetSymbolAddress((void**)&penc, g_enc);
    cudaGetSymbolAddress((void**)&pdgi, g_dgi);
    cudaGetSymbolAddress((void**)&pysin, g_ysin);
    cudaGetSymbolAddress((void**)&ph1, g_h1);
    cudaGetSymbolAddress((void**)&ph2, g_h2);
    cudaGetSymbolAddress((void**)&pcat, g_cat);
    cudaGetSymbolAddress((void**)&plogits, g_logits);

    float* h1buf[2] = { ph1, ph1 + (size_t)kB * kH };
    float* h2buf[2] = { ph2, ph2 + (size_t)kB * kH };

    const dim3 gBig128(kH3 / 128, kTin * kB / 128);   // (24, 512)
    const dim3 gDec128(kH3 / 128, kTout * kB / 128);  // (24, 64)
    const dim3 gMap(kY / 64, kB / 64);                // (16, 4)  -- old 64-tile
    const dim3 gStep(kH / 32, kB / 64);               // (32, 4) = 128 blocks

    // ---- prologue (ncu -s5 -c1 lands on the 3rd gru_step2) ----
    zero_state<<<kB * kH / 256, 256>>>();                                  // #1
    gather_emb<<<(kTin * kB * kE / 4) / 256, 256>>>(emb, x);               // #2
    gemm_nt128<<<gBig128, 256>>>(pA0, eWih0, ebih0, pgi, kTin * kB, kH3, kE); // #3

    // ---- encoder layer 0 ----
    int p1 = 0, p2 = 0;
    for (int t = 0; t < kTin; t++) {                                       // #4..
        gru_step2<<<gStep, 256>>>(pgi + (size_t)t * kB * kH3, eWhh0, ebhh0,
                                  h1buf[p1], h1buf[p1 ^ 1],
                                  pseqA + (size_t)t * kB * kH);
        p1 ^= 1;
    }
    // ---- encoder layer 1 ----
    gemm_nt128<<<gBig128, 256>>>(pseqA, eWih1, ebih1, pgi, kTin * kB, kH3, kH);
    for (int t = 0; t < kTin; t++) {
        gru_step2<<<gStep, 256>>>(pgi + (size_t)t * kB * kH3, eWhh1, ebhh1,
                                  h2buf[p2], h2buf[p2 ^ 1],
                                  penc + (size_t)t * kB * kH);
        p2 ^= 1;
    }
    // h1buf[p1] = enc L0 final hidden; h2buf[p2] = enc L1 final hidden.

    // ---- decoder prep ----
    build_ysin<<<(kTout * kB * kY / 4) / 256, 256>>>(y);
    gemm_nt128<<<gDec128, 256>>>(pysin, dWih0, dbih0, pdgi, kTout * kB, kH3, kY);

    // ---- decoder ----
    for (int t = 0; t < kTout; t++) {
        gru_step2<<<gStep, 256>>>(pdgi + (size_t)t * kB * kH3, dWhh0, dbhh0,
                                  h1buf[p1], h1buf[p1 ^ 1], nullptr);
        p1 ^= 1;
        gru_dual_k<<<gStep, 512>>>(h1buf[p1], dWih1, dbih1,
                                   h2buf[p2], dWhh1, dbhh1,
                                   h2buf[p2 ^ 1], pcat + kH);
        p2 ^= 1;
        attn_kernel<<<kB, 256>>>(h2buf[p2]);
        gemm_nt64<<<gMap, 256>>>(pcat, mapW, mapb, plogits, kB, kY, 2 * kH);
        loss_kernel<<<kB, 256>>>(y, t);
    }

    // ---- epilogue reductions ----
    ysum_part<<<kTout * kB, 256>>>(y);
    ysum_final<<<1, 256>>>();
    final_kernel<<<1, 256>>>(out);
}

// round 17
// speedup vs baseline: 2.7071x; 1.2546x over previous
#include <cuda_runtime.h>
#include <cuda_bf16.h>
#include <cstdint>
#include <cstddef>

// ---------------------------------------------------------------------------
// Problem constants (fixed by the reference)
// ---------------------------------------------------------------------------
namespace {
constexpr int kB    = 256;    // batch
constexpr int kTin  = 256;    // encoder steps
constexpr int kTout = 32;     // decoder steps
constexpr int kE    = 512;    // embedding dim
constexpr int kH    = 1024;   // hidden dim
constexpr int kY    = 1024;   // output feature dim
constexpr int kH3   = 3 * kH; // GRU gate width
}

// ---------------------------------------------------------------------------
// Scratch (device globals -- allocation-free rule)
// ---------------------------------------------------------------------------
__device__ float g_gi[(size_t)kTin * kB * kH3];     // batched input gates  [T*B, 3H]
__device__ float g_seqA[(size_t)kTin * kB * kH];    // encoder layer0 outputs
__device__ float g_enc[(size_t)kTin * kB * kH];    // encoder layer1 outputs (enc_out)
__device__ float g_dgi[(size_t)kTout * kB * kH3];   // decoder L0 batched input gates
__device__ float g_h1[2][kB * kH];                  // ping-pong hidden (layer-A role)
__device__ float g_h2[2][kB * kH];                  // ping-pong hidden (layer-B role)
__device__ float g_cat[kB * 2 * kH];                // [attn | h2]
__device__ float g_logits[kB * kY];
__device__ float g_loss[kTout * kB];
__device__ float g_ypart[kTout * kB];
__device__ float g_ysum;
// bf16 staging buffers for tensor-core gate GEMMs
__device__ __align__(256) __nv_bfloat16 g_A0h[(size_t)kTin * kB * kE];
__device__ __align__(256) __nv_bfloat16 g_seqAh[(size_t)kTin * kB * kH];
__device__ __align__(256) __nv_bfloat16 g_ysinh[(size_t)kTout * kB * kY];
__device__ __align__(256) __nv_bfloat16 g_Wh0[(size_t)kH3 * kE];
__device__ __align__(256) __nv_bfloat16 g_Wh1[(size_t)kH3 * kH];
__device__ __align__(256) __nv_bfloat16 g_Wd0[(size_t)kH3 * kY];

__device__ __forceinline__ uint32_t smem_u32(const void* p) {
    uint32_t a;
    asm("{ .reg .u64 t; cvta.to.shared.u64 t, %1; cvt.u32.u64 %0, t; }" : "=r"(a) : "l"(p));
    return a;
}

// ---------------------------------------------------------------------------
// gemm_bf16_mma: C[M,3072] = A[M,K](bf16) @ W[3072,K](bf16)^T + bias (fp32).
// Baseline-PTX tensor cores: mma.sync m16n8k16 bf16 + ldmatrix (sm_80+ ops,
// compile-safe on the harness's compute_103 target).
// Block: 128(M) x 128(N), 256 threads = 8 warps (4 M x 2 N), warp tile 32x64.
// Smem rows padded to 72 halves (144B = 9 x 16B) -> conflict-free ldmatrix.
// K staged in 64-half chunks; K % 64 == 0 at all call sites (512/1024).
// ---------------------------------------------------------------------------
__global__ void __launch_bounds__(256) gemm_bf16_mma(
    const __nv_bfloat16* __restrict__ A, const __nv_bfloat16* __restrict__ W,
    const float* __restrict__ bias, float* __restrict__ C, int K)
{
    __shared__ __align__(16) __nv_bfloat16 sA[128 * 72];
    __shared__ __align__(16) __nv_bfloat16 sB[128 * 72];

    const int tid = threadIdx.x;
    const int wid = tid >> 5, lane = tid & 31;
    const int wm = wid & 3, wn = wid >> 2;           // 4 x 2 warp grid
    const int m0 = blockIdx.y * 128, n0 = blockIdx.x * 128;

    const uint32_t sAb = smem_u32(sA);
    const uint32_t sBb = smem_u32(sB);

    float acc[2][8][4];
#pragma unroll
    for (int i = 0; i < 2; i++)
#pragma unroll
        for (int j = 0; j < 8; j++)
#pragma unroll
            for (int c = 0; c < 4; c++) acc[i][j][c] = 0.f;

    for (int kc = 0; kc < K; kc += 64) {
#pragma unroll
        for (int t = 0; t < 4; t++) {
            int i = tid + t * 256;              // 0..1023: 128 rows x 8 16B-chunks
            int row = i >> 3, q = (i & 7) * 8;  // q in halves
            *(uint4*)(sA + row * 72 + q) = *(const uint4*)(A + (size_t)(m0 + row) * K + kc + q);
            *(uint4*)(sB + row * 72 + q) = *(const uint4*)(W + (size_t)(n0 + row) * K + kc + q);
        }
        __syncthreads();
#pragma unroll
        for (int k16 = 0; k16 < 4; k16++) {
            uint32_t a[2][4], b[4][4];
            const uint32_t coff = (uint32_t)(k16 * 16 + ((lane >> 4) << 3)) * 2;
#pragma unroll
            for (int mi = 0; mi < 2; mi++) {
                uint32_t addr = sAb + (uint32_t)((wm * 32 + mi * 16 + (lane & 15)) * 72) * 2 + coff;
                asm volatile("ldmatrix.sync.aligned.m8n8.x4.shared.b16 {%0,%1,%2,%3}, [%4];"
                    : "=r"(a[mi][0]), "=r"(a[mi][1]), "=r"(a[mi][2]), "=r"(a[mi][3]) : "r"(addr));
            }
#pragma unroll
            for (int nb = 0; nb < 4; nb++) {
                uint32_t addr = sBb + (uint32_t)((wn * 64 + nb * 16 + (lane & 15)) * 72) * 2 + coff;
                asm volatile("ldmatrix.sync.aligned.m8n8.x4.shared.b16 {%0,%1,%2,%3}, [%4];"
                    : "=r"(b[nb][0]), "=r"(b[nb][1]), "=r"(b[nb][2]), "=r"(b[nb][3]) : "r"(addr));
            }
#pragma unroll
            for (int mi = 0; mi < 2; mi++)
#pragma unroll
                for (int nb = 0; nb < 4; nb++) {
                    // n-tile 2*nb   (n = nb*16 + 0..7) : b fragments {mat0, mat2}
                    asm volatile(
                        "mma.sync.aligned.m16n8k16.row.col.f32.bf16.bf16.f32 "
                        "{%0,%1,%2,%3}, {%4,%5,%6,%7}, {%8,%9}, {%0,%1,%2,%3};"
                        : "+f"(acc[mi][2 * nb][0]), "+f"(acc[mi][2 * nb][1]),
                          "+f"(acc[mi][2 * nb][2]), "+f"(acc[mi][2 * nb][3])
                        : "r"(a[mi][0]), "r"(a[mi][1]), "r"(a[mi][2]), "r"(a[mi][3]),
                          "r"(b[nb][0]), "r"(b[nb][2]));
                    // n-tile 2*nb+1 (n = nb*16 + 8..15): b fragments {mat1, mat3}
                    asm volatile(
                        "mma.sync.aligned.m16n8k16.row.col.f32.bf16.bf16.f32 "
                        "{%0,%1,%2,%3}, {%4,%5,%6,%7}, {%8,%9}, {%0,%1,%2,%3};"
                        : "+f"(acc[mi][2 * nb + 1][0]), "+f"(acc[mi][2 * nb + 1][1]),
                          "+f"(acc[mi][2 * nb + 1][2]), "+f"(acc[mi][2 * nb + 1][3])
                        : "r"(a[mi][0]), "r"(a[mi][1]), "r"(a[mi][2]), "r"(a[mi][3]),
                          "r"(b[nb][1]), "r"(b[nb][3]));
                }
        }
        __syncthreads();
    }

    // Epilogue: c fragment lane map r = lane/4 (and +8), c = (lane%4)*2.
    const int r0 = lane >> 2, c0 = (lane & 3) * 2;
#pragma unroll
    for (int mi = 0; mi < 2; mi++)
#pragma unroll
        for (int nt = 0; nt < 8; nt++) {
            int gr = m0 + wm * 32 + mi * 16 + r0;
            int gc = n0 + wn * 64 + nt * 8 + c0;
            float b0 = bias[gc], b1 = bias[gc + 1];
            float2 o0 = make_float2(acc[mi][nt][0] + b0, acc[mi][nt][1] + b1);
            float2 o1 = make_float2(acc[mi][nt][2] + b0, acc[mi][nt][3] + b1);
            *(float2*)(C + (size_t)gr * kH3 + gc) = o0;
            *(float2*)(C + (size_t)(gr + 8) * kH3 + gc) = o1;
        }
}

// ---------------------------------------------------------------------------
// Reduction helpers (blockDim.x == 256 assumed)
// ---------------------------------------------------------------------------
__device__ __forceinline__ float warp_sum(float v) {
#pragma unroll
    for (int o = 16; o; o >>= 1) v += __shfl_xor_sync(0xffffffffu, v, o);
    return v;
}
__device__ __forceinline__ float warp_max(float v) {
#pragma unroll
    for (int o = 16; o; o >>= 1) v = fmaxf(v, __shfl_xor_sync(0xffffffffu, v, o));
    return v;
}
__device__ __forceinline__ float block_sum(float v, float* red) {
    int l = threadIdx.x & 31, w = threadIdx.x >> 5;
    v = warp_sum(v);
    if (l == 0) red[w] = v;
    __syncthreads();
    float s = 0.f;
#pragma unroll
    for (int i = 0; i < 8; i++) s += red[i];
    __syncthreads();
    return s;
}
__device__ __forceinline__ float block_max(float v, float* red) {
    int l = threadIdx.x & 31, w = threadIdx.x >> 5;
    v = warp_max(v);
    if (l == 0) red[w] = v;
    __syncthreads();
    float s = red[0];
#pragma unroll
    for (int i = 1; i < 8; i++) s = fmaxf(s, red[i]);
    __syncthreads();
    return s;
}
__device__ __forceinline__ float sigmoidf(float x) { return 1.0f / (1.0f + expf(-x)); }

// ---------------------------------------------------------------------------
// gemm_nt64: 64x64x16 fp32 kernel for the small mapping GEMM only.
// ---------------------------------------------------------------------------
__global__ void __launch_bounds__(256) gemm_nt64(
    const float* __restrict__ A, const float* __restrict__ W,
    const float* __restrict__ bias, float* __restrict__ C,
    int M, int N, int K)
{
    constexpr int BK = 16;
    __shared__ float As[BK][68];
    __shared__ float Ws[BK][68];

    const int tid = threadIdx.x;
    const int tx = tid & 15, ty = tid >> 4;
    const int m0 = blockIdx.y * 64, n0 = blockIdx.x * 64;
    const int lrow = tid >> 2;
    const int lk   = (tid & 3) * 4;

    const float* Aptr = A + (size_t)(m0 + lrow) * K + lk;
    const float* Wptr = W + (size_t)(n0 + lrow) * K + lk;

    float acc[4][4] = {};
    for (int k0 = 0; k0 < K; k0 += BK) {
        float4 av = *(const float4*)(Aptr + k0);
        float4 wv = *(const float4*)(Wptr + k0);
        As[lk + 0][lrow] = av.x; As[lk + 1][lrow] = av.y;
        As[lk + 2][lrow] = av.z; As[lk + 3][lrow] = av.w;
        Ws[lk + 0][lrow] = wv.x; Ws[lk + 1][lrow] = wv.y;
        Ws[lk + 2][lrow] = wv.z; Ws[lk + 3][lrow] = wv.w;
        __syncthreads();
#pragma unroll
        for (int k = 0; k < BK; k++) {
            float4 a = *(const float4*)&As[k][ty * 4];
            float4 b = *(const float4*)&Ws[k][tx * 4];
            const float* af = (const float*)&a;
            const float* bf = (const float*)&b;
#pragma unroll
            for (int i = 0; i < 4; i++)
#pragma unroll
                for (int j = 0; j < 4; j++)
                    acc[i][j] += af[i] * bf[j];
        }
        __syncthreads();
    }

    float4 bvv = make_float4(0.f, 0.f, 0.f, 0.f);
    if (bias) bvv = *(const float4*)(bias + n0 + tx * 4);
#pragma unroll
    for (int i = 0; i < 4; i++) {
        float4 o;
        o.x = acc[i][0] + bvv.x; o.y = acc[i][1] + bvv.y;
        o.z = acc[i][2] + bvv.z; o.w = acc[i][3] + bvv.w;
        *(float4*)(C + (size_t)(m0 + ty * 4 + i) * N + n0 + tx * 4) = o;
    }
}

// ---------------------------------------------------------------------------
// gru_step2: fused recurrent GRU step (UNCHANGED from R14-passing version).
// ---------------------------------------------------------------------------
__global__ void __launch_bounds__(256) gru_step2(
    const float* __restrict__ gi, const float* __restrict__ Whh,
    const float* __restrict__ bhh, const float* __restrict__ h_old,
    float* __restrict__ h_new, float* __restrict__ seq_out)
{
    __shared__ float S[6144];
    float* sA = S;
    float* sW = S + 2176;

    const int tid = threadIdx.x;
    const int kg  = tid >> 7;
    const int t   = tid & 127;
    const int tyg = t >> 3;
    const int txg = t & 7;
    const int m0 = blockIdx.y * 64, n0 = blockIdx.x * 32;

    float acc[3][4][4] = {};

    for (int k0 = 0; k0 < 512; k0 += 16) {
#pragma unroll
        for (int i = tid; i < 512; i += 256) {
            int g = i >> 8, rem = i & 255;
            int row = rem >> 2, kq = (rem & 3) * 4;
            float4 v = *(const float4*)(h_old + (size_t)(m0 + row) * kH + g * 512 + k0 + kq);
            float* d = sA + g * 1088;
            d[(kq + 0) * 68 + row] = v.x; d[(kq + 1) * 68 + row] = v.y;
            d[(kq + 2) * 68 + row] = v.z; d[(kq + 3) * 68 + row] = v.w;
        }
#pragma unroll
        for (int i = tid; i < 768; i += 256) {
            int g = (i >= 384) ? 1 : 0;
            int rem = i - g * 384;
            int gate = rem >> 7;
            int r2 = rem & 127;
            int rr = r2 >> 2, kq = (r2 & 3) * 4;
            float4 v = *(const float4*)(Whh + (size_t)(gate * kH + n0 + rr) * kH + g * 512 + k0 + kq);
            float* d = sW + (g * 3 + gate) * 576;
            d[(kq + 0) * 36 + rr] = v.x; d[(kq + 1) * 36 + rr] = v.y;
            d[(kq + 2) * 36 + rr] = v.z; d[(kq + 3) * 36 + rr] = v.w;
        }
        __syncthreads();
        const float* mA = sA + kg * 1088;
        const float* mW = sW + kg * 3 * 576;
#pragma unroll
        for (int kk = 0; kk < 16; kk++) {
            float a[4];
            *(float4*)a = *(const float4*)&mA[kk * 68 + tyg * 4];
#pragma unroll
            for (int gt = 0; gt < 3; gt++) {
                float w[4];
                *(float4*)w = *(const float4*)&mW[gt * 576 + kk * 36 + txg * 4];
#pragma unroll
                for (int r = 0; r < 4; r++)
#pragma unroll
                    for (int c = 0; c < 4; c++)
                        acc[gt][r][c] += a[r] * w[c];
            }
        }
        __syncthreads();
    }

    if (kg == 1) {
        float* d = S + t * 48;
#pragma unroll
        for (int gt = 0; gt < 3; gt++)
#pragma unroll
            for (int r = 0; r < 4; r++)
#pragma unroll
                for (int c = 0; c < 4; c++)
                    d[gt * 16 + r * 4 + c] = acc[gt][r][c];
    }
    __syncthreads();
    if (kg == 0) {
        const float* d = S + t * 48;
#pragma unroll
        for (int gt = 0; gt < 3; gt++)
#pragma unroll
            for (int r = 0; r < 4; r++)
#pragma unroll
                for (int c = 0; c < 4; c++)
                    acc[gt][r][c] += d[gt * 16 + r * 4 + c];

        const int j = n0 + txg * 4;
        float br[4], bz[4], bn[4];
        *(float4*)br = *(const float4*)(bhh + j);
        *(float4*)bz = *(const float4*)(bhh + kH + j);
        *(float4*)bn = *(const float4*)(bhh + 2 * kH + j);
#pragma unroll
        for (int r = 0; r < 4; r++) {
            const int b = m0 + tyg * 4 + r;
            const float* gib = gi + (size_t)b * kH3;
            float gr[4], gz[4], gn[4], hv[4], o[4];
            *(float4*)gr = *(const float4*)(gib + j);
            *(float4*)gz = *(const float4*)(gib + kH + j);
            *(float4*)gn = *(const float4*)(gib + 2 * kH + j);
            *(float4*)hv = *(const float4*)(h_old + (size_t)b * kH + j);
#pragma unroll
            for (int c = 0; c < 4; c++) {
                float rr = sigmoidf(gr[c] + acc[0][r][c] + br[c]);
                float zz = sigmoidf(gz[c] + acc[1][r][c] + bz[c]);
                float nn = tanhf(gn[c] + rr * (acc[2][r][c] + bn[c]));
                o[c] = (1.0f - zz) * nn + zz * hv[c];
            }
            *(float4*)(h_new + (size_t)b * kH + j) = *(float4*)o;
            if (seq_out) *(float4*)(seq_out + (size_t)b * kH + j) = *(float4*)o;
        }
    }
}

// ---------------------------------------------------------------------------
// gru_dual_k: 512-thread dual-GEMM GRU step (decoder L1; UNCHANGED).
// ---------------------------------------------------------------------------
__global__ void __launch_bounds__(512) gru_dual_k(
    const float* __restrict__ x,   const float* __restrict__ Wih,
    const float* __restrict__ bih, const float* __restrict__ h_old,
    const float* __restrict__ Whh, const float* __restrict__ bhh,
    float* __restrict__ h_new,     float* __restrict__ cat_out)
{
    __shared__ float sA[2 * 1088];
    __shared__ float sW[6 * 16 * 36];

    const int tid = threadIdx.x;
    const int m0 = blockIdx.y * 64, n0 = blockIdx.x * 32;
    const int tx = tid & 7, ty = tid >> 3;

    float acc[6][4] = {};
    for (int k0 = 0; k0 < kH; k0 += 16) {
        {
            int buf = tid >> 8, rr = (tid >> 2) & 63, kk = (tid & 3) * 4;
            const float* src = buf ? h_old : x;
            float4 av = *(const float4*)(src + (size_t)(m0 + rr) * kH + k0 + kk);
            float* dst = sA + buf * 1088;
            dst[(kk + 0) * 68 + rr] = av.x; dst[(kk + 1) * 68 + rr] = av.y;
            dst[(kk + 2) * 68 + rr] = av.z; dst[(kk + 3) * 68 + rr] = av.w;
        }
        for (int i = tid; i < 768; i += 512) {
            int s = i >> 7, rr = (i >> 2) & 31, kk = (i & 3) * 4;
            const float* Wsrc = (s < 3) ? Wih : Whh;
            int g = (s < 3) ? s : s - 3;
            float4 wv = *(const float4*)(Wsrc + (size_t)(g * kH + n0 + rr) * kH + k0 + kk);
            sW[(s * 16 + kk + 0) * 36 + rr] = wv.x; sW[(s * 16 + kk + 1) * 36 + rr] = wv.y;
            sW[(s * 16 + kk + 2) * 36 + rr] = wv.z; sW[(s * 16 + kk + 3) * 36 + rr] = wv.w;
        }
        __syncthreads();
#pragma unroll
        for (int k = 0; k < 16; k++) {
            float ax = sA[k * 68 + ty];
            float ah = sA[1088 + k * 68 + ty];
#pragma unroll
            for (int s = 0; s < 6; s++) {
                float4 w = *(const float4*)&sW[(s * 16 + k) * 36 + tx * 4];
                float a = (s < 3) ? ax : ah;
                acc[s][0] += a * w.x; acc[s][1] += a * w.y;
                acc[s][2] += a * w.z; acc[s][3] += a * w.w;
            }
        }
        __syncthreads();
    }

    const int j = n0 + tx * 4;
    const float4 bir = *(const float4*)(bih + j);
    const float4 biz = *(const float4*)(bih + kH + j);
    const float4 bin = *(const float4*)(bih + 2 * kH + j);
    const float4 bhr = *(const float4*)(bhh + j);
    const float4 bhz = *(const float4*)(bhh + kH + j);
    const float4 bhn = *(const float4*)(bhh + 2 * kH + j);
    float4 hv = *(const float4*)(h_old + (size_t)(m0 + ty) * kH + j);
    float4 o;
    float* op = (float*)&o;
    const float* hvp = (const float*)&hv;
    const float* birp = (const float*)&bir; const float* bizp = (const float*)&biz;
    const float* binp = (const float*)&bin; const float* bhrp = (const float*)&bhr;
    const float* bhzp = (const float*)&bhz; const float* bhnp = (const float*)&bhn;
#pragma unroll
    for (int c = 0; c < 4; c++) {
        float r = sigmoidf(acc[0][c] + birp[c] + acc[3][c] + bhrp[c]);
        float z = sigmoidf(acc[1][c] + bizp[c] + acc[4][c] + bhzp[c]);
        float n = tanhf(acc[2][c] + binp[c] + r * (acc[5][c] + bhnp[c]));
        op[c] = (1.0f - z) * n + z * hvp[c];
    }
    const int b = m0 + ty;
    *(float4*)(h_new + (size_t)b * kH + j) = o;
    *(float4*)(cat_out + (size_t)b * 2 * kH + j) = o;
}

// ---------------------------------------------------------------------------
// Gather / shift / convert / init / reductions
// ---------------------------------------------------------------------------
__global__ void gather_emb_h(const float* __restrict__ emb, const int* __restrict__ x)
{
    int idx = blockIdx.x * blockDim.x + threadIdx.x;   // over T*B*E/4
    int col = idx & (kE / 4 - 1);
    int row = idx >> 7;
    int t = row >> 8;
    int b = row & (kB - 1);
    int tok = x[b * kTin + t];
    float4 v = ((const float4*)emb)[(size_t)tok * (kE / 4) + col];
    __nv_bfloat162* dst = (__nv_bfloat162*)(g_A0h + (size_t)row * kE + col * 4);
    dst[0] = __floats2bfloat162_rn(v.x, v.y);
    dst[1] = __floats2bfloat162_rn(v.z, v.w);
}

__global__ void build_ysin_h(const float* __restrict__ y)
{
    int idx = blockIdx.x * blockDim.x + threadIdx.x;   // over Tout*B*Y/4
    int col = idx & (kY / 4 - 1);
    int row = idx >> 8;
    int t = row >> 8;
    int b = row & (kB - 1);
    float4 v = make_float4(0.f, 0.f, 0.f, 0.f);
    if (t > 0) v = ((const float4*)y)[((size_t)b * kTout + (t - 1)) * (kY / 4) + col];
    __nv_bfloat162* dst = (__nv_bfloat162*)(g_ysinh + (size_t)row * kY + col * 4);
    dst[0] = __floats2bfloat162_rn(v.x, v.y);
    dst[1] = __floats2bfloat162_rn(v.z, v.w);
}

__global__ void f2b(const float* __restrict__ src, __nv_bfloat16* __restrict__ dst, int n4)
{
    int i = blockIdx.x * blockDim.x + threadIdx.x;
    if (i >= n4) return;
    float4 v = ((const float4*)src)[i];
    __nv_bfloat162* d = (__nv_bfloat162*)(dst + (size_t)i * 4);
    d[0] = __floats2bfloat162_rn(v.x, v.y);
    d[1] = __floats2bfloat162_rn(v.z, v.w);
}

__global__ void zero_state()
{
    int i = blockIdx.x * blockDim.x + threadIdx.x;
    g_h1[0][i] = 0.f; g_h2[0][i] = 0.f;
}

__global__ void ysum_part(const float* __restrict__ y)
{
    __shared__ float red[8];
    int blk = blockIdx.x, tid = threadIdx.x;
    const float* p = y + (size_t)blk * 1024;
    float s = p[tid] + p[tid + 256] + p[tid + 512] + p[tid + 768];
    s = block_sum(s, red);
    if (tid == 0) g_ypart[blk] = s;
}
__global__ void ysum_final()
{
    __shared__ float red[8];
    int tid = threadIdx.x;
    float s = 0.f;
    for (int i = tid; i < kTout * kB; i += 256) s += g_ypart[i];
    s = block_sum(s, red);
    if (tid == 0) g_ysum = s;
}

// ---------------------------------------------------------------------------
// Attention (unchanged)
// ---------------------------------------------------------------------------
__global__ void attn_kernel(const float* __restrict__ h2)
{
    __shared__ float sh[kH];
    __shared__ float sc[kTin];
    __shared__ float red[16];
    int b = blockIdx.x, tid = threadIdx.x;
    int w = tid >> 5, l = tid & 31;

#pragma unroll
    for (int q = 0; q < 4; q++) sh[tid + 256 * q] = h2[b * kH + tid + 256 * q];
    __syncthreads();

    for (int si = 0; si < 32; si++) {
        int s = w * 32 + si;
        const float* row = g_enc + ((size_t)s * kB + b) * kH;
        float acc = 0.f;
#pragma unroll 8
        for (int k = 0; k < 32; k++) acc += row[l + 32 * k] * sh[l + 32 * k];
        acc = warp_sum(acc);
        if (l == 0) sc[s] = acc;
    }
    __syncthreads();

    float v = sc[tid];
    float m = warp_max(v);
    if (l == 0) red[w] = m;
    __syncthreads();
    float bm = red[0];
#pragma unroll
    for (int i = 1; i < 8; i++) bm = fmaxf(bm, red[i]);
    float p = expf(v - bm);
    sc[tid] = p;
    float ps = warp_sum(p);
    if (l == 0) red[8 + w] = ps;
    __syncthreads();
    float tot = 0.f;
#pragma unroll
    for (int i = 0; i < 8; i++) tot += red[8 + i];

    float a0 = 0.f, a1 = 0.f, a2 = 0.f, a3 = 0.f;
#pragma unroll 4
    for (int s = 0; s < kTin; s++) {
        float pr = sc[s];
        const float* row = g_enc + ((size_t)s * kB + b) * kH;
        a0 += pr * row[tid];       a1 += pr * row[tid + 256];
        a2 += pr * row[tid + 512]; a3 += pr * row[tid + 768];
    }
    float inv = 1.0f / tot;
    float* cb = g_cat + b * 2 * kH;
    cb[tid] = a0 * inv; cb[tid + 256] = a1 * inv;
    cb[tid + 512] = a2 * inv; cb[tid + 768] = a3 * inv;
}

// ---------------------------------------------------------------------------
// Per-step NLL + final (unchanged)
// ---------------------------------------------------------------------------
__global__ void loss_kernel(const float* __restrict__ y, int t)
{
    __shared__ float red[8];
    int b = blockIdx.x, tid = threadIdx.x;
    const float* lr = g_logits + b * kY;
    float l0 = lr[tid], l1 = lr[tid + 256], l2 = lr[tid + 512], l3 = lr[tid + 768];
    float m = block_max(fmaxf(fmaxf(l0, l1), fmaxf(l2, l3)), red);
    float se = block_sum(expf(l0 - m) + expf(l1 - m) + expf(l2 - m) + expf(l3 - m), red);
    float lse = m + logf(se);
    const float* yr = y + ((size_t)b * kTout + t) * kY;
    float a = yr[tid] * (lse - l0) + yr[tid + 256] * (lse - l1)
            + yr[tid + 512] * (lse - l2) + yr[tid + 768] * (lse - l3);
    a = block_sum(a, red);
    if (tid == 0) g_loss[t * kB + b] = a;
}

__global__ void final_kernel(float* __restrict__ out)
{
    __shared__ float red[8];
    int tid = threadIdx.x;
    float s = 0.f;
    for (int i = tid; i < kTout * kB; i += 256) s += g_loss[i];
    s = block_sum(s, red);
    if (tid == 0) out[0] = s / g_ysum;
}

// ---------------------------------------------------------------------------
// Orchestration
// ---------------------------------------------------------------------------
extern "C" void kernel_launch(void* const* d_in, const int* in_sizes, int n_in,
                              void* d_out, int out_size)
{
    const int*   x    = (const int*)d_in[0];
    const float* y    = (const float*)d_in[1];
    const float* emb  = (const float*)d_in[2];
    const float* eWih0 = (const float*)d_in[3],  *eWhh0 = (const float*)d_in[4];
    const float* ebih0 = (const float*)d_in[5],  *ebhh0 = (const float*)d_in[6];
    const float* eWih1 = (const float*)d_in[7],  *eWhh1 = (const float*)d_in[8];
    const float* ebih1 = (const float*)d_in[9],  *ebhh1 = (const float*)d_in[10];
    const float* dWih0 = (const float*)d_in[11], *dWhh0 = (const float*)d_in[12];
    const float* dbih0 = (const float*)d_in[13], *dbhh0 = (const float*)d_in[14];
    const float* dWih1 = (const float*)d_in[15], *dWhh1 = (const float*)d_in[16];
    const float* dbih1 = (const float*)d_in[17], *dbhh1 = (const float*)d_in[18];
    const float* mapW  = (const float*)d_in[19], *mapb  = (const float*)d_in[20];
    float* out = (float*)d_out;

    float *pgi, *pseqA, *penc, *pdgi, *ph1, *ph2, *pcat, *plogits;
    __nv_bfloat16 *pA0h, *pseqAh, *pysinh, *pWh0, *pWh1, *pWd0;
    cudaGetSymbolAddress((void**)&pgi, g_gi);
    cudaGetSymbolAddress((void**)&pseqA, g_seqA);
    cudaGetSymbolAddress((void**)&penc, g_enc);
    cudaGetSymbolAddress((void**)&pdgi, g_dgi);
    cudaGetSymbolAddress((void**)&ph1, g_h1);
    cudaGetSymbolAddress((void**)&ph2, g_h2);
    cudaGetSymbolAddress((void**)&pcat, g_cat);
    cudaGetSymbolAddress((void**)&plogits, g_logits);
    cudaGetSymbolAddress((void**)&pA0h, g_A0h);
    cudaGetSymbolAddress((void**)&pseqAh, g_seqAh);
    cudaGetSymbolAddress((void**)&pysinh, g_ysinh);
    cudaGetSymbolAddress((void**)&pWh0, g_Wh0);
    cudaGetSymbolAddress((void**)&pWh1, g_Wh1);
    cudaGetSymbolAddress((void**)&pWd0, g_Wd0);

    float* h1buf[2] = { ph1, ph1 + (size_t)kB * kH };
    float* h2buf[2] = { ph2, ph2 + (size_t)kB * kH };

    const dim3 gTC(kH3 / 128, kTin * kB / 128);       // (24, 512)
    const dim3 gTCdec(kH3 / 128, kTout * kB / 128);   // (24, 64)
    const dim3 gMap(kY / 64, kB / 64);                // (16, 4)
    const dim3 gStep(kH / 32, kB / 64);               // (32, 4) = 128 blocks

    // ---- prologue (ncu -s5 -c1 lands on launch #6 = first gemm_bf16_mma) ----
    zero_state<<<kB * kH / 256, 256>>>();                                     // #1
    gather_emb_h<<<(kTin * kB * kE / 4) / 256, 256>>>(emb, x);                // #2
    f2b<<<(kH3 * kE / 4) / 256, 256>>>(eWih0, pWh0, kH3 * kE / 4);            // #3
    f2b<<<(kH3 * kH / 4) / 256, 256>>>(eWih1, pWh1, kH3 * kH / 4);            // #4
    f2b<<<(kH3 * kY / 4) / 256, 256>>>(dWih0, pWd0, kH3 * kY / 4);            // #5
    gemm_bf16_mma<<<gTC, 256>>>(pA0h, pWh0, ebih0, pgi, kE);                  // #6 (captured)

    // ---- encoder layer 0 ----
    int p1 = 0, p2 = 0;
    for (int t = 0; t < kTin; t++) {
        gru_step2<<<gStep, 256>>>(pgi + (size_t)t * kB * kH3, eWhh0, ebhh0,
                                  h1buf[p1], h1buf[p1 ^ 1],
                                  pseqA + (size_t)t * kB * kH);
        p1 ^= 1;
    }
    // ---- encoder layer 1 ----
    f2b<<<((size_t)kTin * kB * kH / 4) / 256, 256>>>(pseqA, pseqAh, kTin * kB * kH / 4);
    gemm_bf16_mma<<<gTC, 256>>>(pseqAh, pWh1, ebih1, pgi, kH);
    for (int t = 0; t < kTin; t++) {
        gru_step2<<<gStep, 256>>>(pgi + (size_t)t * kB * kH3, eWhh1, ebhh1,
                                  h2buf[p2], h2buf[p2 ^ 1],
                                  penc + (size_t)t * kB * kH);
        p2 ^= 1;
    }
    // h1buf[p1] = enc L0 final hidden; h2buf[p2] = enc L1 final hidden.

    // ---- decoder prep ----
    build_ysin_h<<<(kTout * kB * kY / 4) / 256, 256>>>(y);
    gemm_bf16_mma<<<gTCdec, 256>>>(pysinh, pWd0, dbih0, pdgi, kY);

    // ---- decoder ----
    for (int t = 0; t < kTout; t++) {
        gru_step2<<<gStep, 256>>>(pdgi + (size_t)t * kB * kH3, dWhh0, dbhh0,
                                  h1buf[p1], h1buf[p1 ^ 1], nullptr);
        p1 ^= 1;
        gru_dual_k<<<gStep, 512>>>(h1buf[p1], dWih1, dbih1,
                                   h2buf[p2], dWhh1, dbhh1,
                                   h2buf[p2 ^ 1], pcat + kH);
        p2 ^= 1;
        attn_kernel<<<kB, 256>>>(h2buf[p2]);
        gemm_nt64<<<gMap, 256>>>(pcat, mapW, mapb, plogits, kB, kY, 2 * kH);
        loss_kernel<<<kB, 256>>>(y, t);
    }

    // ---- epilogue reductions ----
    ysum_part<<<kTout * kB, 256>>>(y);
    ysum_final<<<1, 256>>>();
    final_kernel<<<1, 256>>>(out);
}